// round 14
// baseline (speedup 1.0000x reference)
#include <cuda_runtime.h>
#include <cuda_fp16.h>
#include <math.h>
#include <stdint.h>

// ---------------- problem constants ----------------
#define B_    32
#define M_    512
#define E_    512
#define S_    513
#define NTOK  (B_*S_)          // 16416
#define NHEAD_ 8
#define DH_   64
#define DFF_  2048
#define F_    768

// ---------------- scratch ----------------
__device__ float d_PE[M_*E_];
__device__ int   d_SPAN[B_*M_];

// ---------------- fp16 activation / weight buffers ----------------
__device__ __align__(16) __half d_Xf   [(size_t)NTOK*E_];
__device__ __align__(16) __half d_Yh   [(size_t)NTOK*E_];
__device__ __align__(16) __half d_QKVf [(size_t)NTOK*3*E_];
__device__ __align__(16) __half d_CXf  [(size_t)NTOK*E_];
__device__ __align__(16) __half d_Hf   [(size_t)NTOK*DFF_];
__device__ __align__(16) __half d_POSFh[(size_t)NTOK*F_];
__device__ __align__(16) __half d_WQf  [(size_t)2*3*E_*E_];
__device__ __align__(16) __half d_WOf  [(size_t)2*E_*E_];
__device__ __align__(16) __half d_W1f  [(size_t)2*DFF_*E_];
__device__ __align__(16) __half d_W2f  [(size_t)2*E_*DFF_];
__device__ __align__(16) __half d_WMf  [(size_t)F_*E_];

// ================= fp16 tensor-core GEMM (BK=64, 2 CTAs/SM, frag pipelined) ====
#define BM 128
#define BN 128
#define BK 64
#define PADB 144
#define A_ARR (128*PADB)
#define B_ARR (128*PADB)
#define STAGE (A_ARR + B_ARR)
#define NSTAGE 3
#define SMEM_GEMM (NSTAGE*STAGE)
#define NTHR_G 256

__device__ __forceinline__ uint32_t smem_u32(const void* p) {
    uint32_t a;
    asm("{ .reg .u64 t; cvta.to.shared.u64 t, %1; cvt.u32.u64 %0, t; }"
        : "=r"(a) : "l"(p));
    return a;
}
__device__ __forceinline__ void ldsm4(uint32_t* r, uint32_t addr) {
    asm volatile("ldmatrix.sync.aligned.m8n8.x4.shared.b16 {%0,%1,%2,%3}, [%4];"
        : "=r"(r[0]), "=r"(r[1]), "=r"(r[2]), "=r"(r[3]) : "r"(addr));
}
__device__ __forceinline__ void mma16816(float* c, const uint32_t* a, const uint32_t* b) {
    asm volatile(
        "mma.sync.aligned.m16n8k16.row.col.f32.f16.f16.f32 "
        "{%0,%1,%2,%3}, {%4,%5,%6,%7}, {%8,%9}, {%0,%1,%2,%3};"
        : "+f"(c[0]), "+f"(c[1]), "+f"(c[2]), "+f"(c[3])
        : "r"(a[0]), "r"(a[1]), "r"(a[2]), "r"(a[3]), "r"(b[0]), "r"(b[1]));
}
__device__ __forceinline__ void cpa16(uint32_t dst, const void* src, int srcsize) {
    asm volatile("cp.async.cg.shared.global [%0], [%1], 16, %2;"
                 :: "r"(dst), "l"(src), "r"(srcsize));
}

__device__ __forceinline__ void load_stage(
    uint32_t st,
    const __half* __restrict__ Af, const __half* __restrict__ Bf,
    int tile_m, int tile_n, int Mdim, int Kdim, int kc, int tid)
{
    const int k0 = kc * BK;
    #pragma unroll
    for (int i = 0; i < 4; i++) {
        int id = tid + NTHR_G*i;
        int row = id >> 3, c = id & 7;
        const __half* src = Af + (size_t)(tile_m + row) * Kdim + k0 + c*8;
        cpa16(st + row*PADB + c*16, src, (tile_m + row) < Mdim ? 16 : 0);
    }
    #pragma unroll
    for (int i = 0; i < 4; i++) {
        int id = tid + NTHR_G*i;
        int row = id >> 3, c = id & 7;
        const __half* src = Bf + (size_t)(tile_n + row) * Kdim + k0 + c*8;
        cpa16(st + A_ARR + row*PADB + c*16, src, 16);
    }
    asm volatile("cp.async.commit_group;" ::: "memory");
}

__device__ __forceinline__ void load_frags(
    uint32_t st, uint32_t a_off, uint32_t b_off, int ks,
    uint32_t (*ah)[4], uint32_t (*bh)[2])
{
    #pragma unroll
    for (int mi = 0; mi < 4; mi++)
        ldsm4(ah[mi], st + a_off + mi * (16 * PADB) + ks * 32);
    #pragma unroll
    for (int p = 0; p < 2; p++) {
        uint32_t r[4];
        ldsm4(r, st + A_ARR + b_off + p * (16 * PADB) + ks * 32);
        bh[2*p][0] = r[0]; bh[2*p][1] = r[1];
        bh[2*p+1][0] = r[2]; bh[2*p+1][1] = r[3];
    }
}

__global__ __launch_bounds__(NTHR_G, 2)
void gemm_tc(const __half* __restrict__ Af, const __half* __restrict__ Bf,
             float* __restrict__ Cf, __half* __restrict__ Chalf,
             int Mdim, int Ndim, int Kdim,
             const float* __restrict__ bias, int act)
{
    extern __shared__ __align__(16) char smem[];
    const uint32_t sb = smem_u32(smem);
    const int tid    = threadIdx.x;
    const int tile_m = blockIdx.y * BM;
    const int tile_n = blockIdx.x * BN;
    const int warp = tid >> 5, lane = tid & 31;
    const int wm2 = warp >> 2, wn4 = warp & 3;

    float acc[4][4][4];
    #pragma unroll
    for (int a = 0; a < 4; a++)
        #pragma unroll
        for (int b = 0; b < 4; b++)
            #pragma unroll
            for (int q = 0; q < 4; q++) acc[a][b][q] = 0.0f;

    const int nst = Kdim / BK;
    load_stage(sb,         Af, Bf, tile_m, tile_n, Mdim, Kdim, 0, tid);
    load_stage(sb + STAGE, Af, Bf, tile_m, tile_n, Mdim, Kdim, 1, tid);

    const uint32_t a_off = (uint32_t)(wm2*64 + (lane & 7) + ((lane >> 3) & 1) * 8) * PADB
                         + ((lane >> 4) * 16);
    const uint32_t b_off = (uint32_t)(wn4*32 + (lane & 7) + ((lane >> 4) & 1) * 8) * PADB
                         + (((lane >> 3) & 1) * 16);

    uint32_t ah[2][4][4], bh[2][4][2];   // double-buffered fragments

    for (int s = 0; s < nst; s++) {
        if (s + 1 < nst) asm volatile("cp.async.wait_group 1;" ::: "memory");
        else             asm volatile("cp.async.wait_group 0;" ::: "memory");
        __syncthreads();
        if (s + 2 < nst)
            load_stage(sb + ((s + 2) % NSTAGE) * STAGE, Af, Bf,
                       tile_m, tile_n, Mdim, Kdim, s + 2, tid);
        const uint32_t st = sb + (s % NSTAGE) * STAGE;

        load_frags(st, a_off, b_off, 0, ah[0], bh[0]);   // prologue: ks=0
        #pragma unroll
        for (int ks = 0; ks < 4; ks++) {
            const int cur = ks & 1, nxt = cur ^ 1;
            if (ks < 3)
                load_frags(st, a_off, b_off, ks + 1, ah[nxt], bh[nxt]);
            #pragma unroll
            for (int mi = 0; mi < 4; mi++)
                #pragma unroll
                for (int ni = 0; ni < 4; ni++)
                    mma16816(acc[mi][ni], ah[cur][mi], bh[cur][ni]);
        }
    }

    // ---- epilogue ----
    const int er = lane >> 2;
    const int ec = (lane & 3) * 2;
    #pragma unroll
    for (int mi = 0; mi < 4; mi++) {
        const int gm0 = tile_m + wm2*64 + mi*16 + er;
        #pragma unroll
        for (int ni = 0; ni < 4; ni++) {
            const int gn = tile_n + wn4*32 + ni*8 + ec;
            float bx = 0.f, by = 0.f;
            if (bias) { float2 bb = *reinterpret_cast<const float2*>(bias + gn);
                        bx = bb.x; by = bb.y; }
            float v0 = acc[mi][ni][0] + bx, v1 = acc[mi][ni][1] + by;
            float v2 = acc[mi][ni][2] + bx, v3 = acc[mi][ni][3] + by;
            if (act == 1) {
                v0 = fmaxf(v0, 0.f); v1 = fmaxf(v1, 0.f);
                v2 = fmaxf(v2, 0.f); v3 = fmaxf(v3, 0.f);
            } else if (act == 2) {
                v0 = tanhf(v0); v1 = tanhf(v1); v2 = tanhf(v2); v3 = tanhf(v3);
            }
            if (Cf) {
                if (gm0 < Mdim)
                    *reinterpret_cast<float2*>(Cf + (size_t)gm0 * Ndim + gn) = make_float2(v0, v1);
                if (gm0 + 8 < Mdim)
                    *reinterpret_cast<float2*>(Cf + (size_t)(gm0+8) * Ndim + gn) = make_float2(v2, v3);
            }
            if (Chalf) {
                if (gm0 < Mdim) {
                    __half2 h; h.x = __float2half_rn(v0); h.y = __float2half_rn(v1);
                    *reinterpret_cast<__half2*>(Chalf + (size_t)gm0 * Ndim + gn) = h;
                }
                if (gm0 + 8 < Mdim) {
                    __half2 h; h.x = __float2half_rn(v2); h.y = __float2half_rn(v3);
                    *reinterpret_cast<__half2*>(Chalf + (size_t)(gm0+8) * Ndim + gn) = h;
                }
            }
        }
    }
}

// ---------------- fp32 -> fp16 convert (multi-tensor) ----------------
__device__ __forceinline__ void cvt_one(const float* in, __half* o, int i) {
    float4 v = *reinterpret_cast<const float4*>(in + (size_t)i * 4);
    __half2 h0, h1;
    h0.x = __float2half_rn(v.x); h0.y = __float2half_rn(v.y);
    h1.x = __float2half_rn(v.z); h1.y = __float2half_rn(v.w);
    uint2 u;
    u.x = *reinterpret_cast<uint32_t*>(&h0);
    u.y = *reinterpret_cast<uint32_t*>(&h1);
    *reinterpret_cast<uint2*>(o + (size_t)i * 4) = u;
}
__global__ void cvt3_kernel(const float* i1, __half* o1, int n1,
                            const float* i2, __half* o2, int n2,
                            const float* i3, __half* o3, int n3) {
    int i = blockIdx.x * blockDim.x + threadIdx.x;
    if (i < n1) { cvt_one(i1, o1, i); return; }
    i -= n1;
    if (i < n2) { cvt_one(i2, o2, i); return; }
    i -= n2;
    if (i < n3) cvt_one(i3, o3, i);
}
__global__ void cvt2_kernel(const float* i1, __half* o1, int n1,
                            const float* i2, __half* o2, int n2) {
    int i = blockIdx.x * blockDim.x + threadIdx.x;
    if (i < n1) { cvt_one(i1, o1, i); return; }
    i -= n1;
    if (i < n2) cvt_one(i2, o2, i);
}

// ---------------- fused span-id + PE table ----------------
__global__ void spanpe_kernel(const int* __restrict__ pos1, int* __restrict__ span,
                              float* __restrict__ pe) {
    if (blockIdx.x < 32) {
        int b = blockIdx.x;
        int j = threadIdx.x;
        __shared__ int firstZero;
        span[b*M_ + j] = -1;
        if (j == 0) firstZero = M_;
        __syncthreads();
        int endv = pos1[((size_t)b*M_ + j)*2 + 1];
        if (endv == 0) atomicMin(&firstZero, j);
        __syncthreads();
        if (j < firstZero) {
            int st = pos1[((size_t)b*M_ + j)*2];
            int en = endv; if (en > M_) en = M_;
            for (int k = st; k < en; k++)
                atomicMax(&span[b*M_ + k], j);
        }
    } else {
        int idx = (blockIdx.x - 32) * 512 + threadIdx.x;
        if (idx >= M_ * E_) return;
        int pos = idx / E_, i = idx % E_;
        double e2  = (double)((i / 2) * 2);
        double ang = (double)pos / pow(10000.0, e2 / (double)E_);
        pe[idx] = (float)((i % 2 == 0) ? sin(ang) : cos(ang));
    }
}

// ---------------- build x [B,S,E] -> fp16 ----------------
__global__ void build_x_kernel(const int* __restrict__ pos2,
                               const float* __restrict__ fbase,
                               const float* __restrict__ emb,
                               const int* __restrict__ span,
                               const float* __restrict__ pe,
                               __half* __restrict__ Xf) {
    int row = blockIdx.x;
    int b = row / S_, s = row % S_;
    size_t base = (size_t)row * E_;
    int e = threadIdx.x;
    float val;
    if (s == 0) {
        val = emb[(size_t)1*E_ + e];
    } else {
        int k = s - 1;
        int sid = span[b*M_ + k];
        if (sid >= 0) {
            int p = pos2[b*M_ + sid];
            val = (p == 0 ? 0.0f : emb[(size_t)p*E_ + e]) + pe[(size_t)sid*E_ + e];
        } else {
            val = fbase[((size_t)b*M_ + k)*E_ + e];
        }
    }
    Xf[base + e] = __float2half_rn(val);
}

// ---------------- fused attention over the B axis ----------------
__global__ void attn_kernel(const __half* __restrict__ QKV,
                            __half* __restrict__ CXf) {
    int z = blockIdx.x;
    int s = z / NHEAD_, h = z % NHEAD_;
    __shared__ float q[B_][DH_];
    __shared__ float k[B_][DH_ + 1];   // pad: conflict-free scores
    __shared__ float v[B_][DH_];
    __shared__ float sc[B_][B_ + 1];

    const __half* base = QKV + (size_t)s * 3*E_ + (size_t)h * DH_;
    int t = threadIdx.x;

    for (int i = t; i < B_*(DH_/2); i += 256) {
        int b = i / (DH_/2), d2 = i % (DH_/2);
        size_t off = (size_t)b * S_ * 3*E_ + 2*d2;
        __half2 hq = *reinterpret_cast<const __half2*>(base + off);
        __half2 hk = *reinterpret_cast<const __half2*>(base + off + E_);
        __half2 hv = *reinterpret_cast<const __half2*>(base + off + 2*E_);
        q[b][2*d2] = __half2float(hq.x); q[b][2*d2+1] = __half2float(hq.y);
        k[b][2*d2] = __half2float(hk.x); k[b][2*d2+1] = __half2float(hk.y);
        v[b][2*d2] = __half2float(hv.x); v[b][2*d2+1] = __half2float(hv.y);
    }
    __syncthreads();

    for (int i = t; i < B_*B_; i += 256) {
        int l = i / B_, m = i % B_;
        float acc = 0.0f;
        #pragma unroll
        for (int d = 0; d < DH_; d++) acc += q[l][d] * k[m][d];
        sc[l][m] = acc * 0.125f;
    }
    __syncthreads();

    int warp = t >> 5, lane = t & 31;
    for (int l = warp; l < B_; l += 8) {
        float val = sc[l][lane];
        float mx = val;
        #pragma unroll
        for (int o = 16; o; o >>= 1) mx = fmaxf(mx, __shfl_xor_sync(0xffffffffu, mx, o));
        float e = expf(val - mx);
        float sum = e;
        #pragma unroll
        for (int o = 16; o; o >>= 1) sum += __shfl_xor_sync(0xffffffffu, sum, o);
        sc[l][lane] = e / sum;
    }
    __syncthreads();

    for (int i = t; i < B_*DH_; i += 256) {
        int l = i / DH_, d = i % DH_;
        float acc = 0.0f;
        #pragma unroll
        for (int m = 0; m < B_; m++) acc += sc[l][m] * v[m][d];
        CXf[((size_t)l * S_ + s) * E_ + (size_t)h * DH_ + d] = __float2half_rn(acc);
    }
}

// ---------------- residual add + layernorm: all-fp16 IO, warp per row ------
__global__ void add_ln_kernel(__half* __restrict__ Xf, const __half* __restrict__ Yh,
                              const float* __restrict__ w, const float* __restrict__ b) {
    int row  = blockIdx.x * 8 + (threadIdx.x >> 5);
    int lane = threadIdx.x & 31;
    const uint4* xr = reinterpret_cast<const uint4*>(Xf + (size_t)row * E_);
    const uint4* yr = reinterpret_cast<const uint4*>(Yh + (size_t)row * E_);

    float vals[16];
    float s = 0.f, s2 = 0.f;
    #pragma unroll
    for (int j = 0; j < 2; j++) {
        uint4 xa = xr[lane + 32*j];
        uint4 ya = yr[lane + 32*j];
        const __half2* xh = reinterpret_cast<const __half2*>(&xa);
        const __half2* yh = reinterpret_cast<const __half2*>(&ya);
        #pragma unroll
        for (int q = 0; q < 4; q++) {
            float2 fx = __half22float2(xh[q]);
            float2 fy = __half22float2(yh[q]);
            float a0 = fx.x + fy.x, a1 = fx.y + fy.y;
            vals[j*8 + 2*q]     = a0;
            vals[j*8 + 2*q + 1] = a1;
            s  += a0 + a1;
            s2 += a0*a0 + a1*a1;
        }
    }
    #pragma unroll
    for (int o = 16; o; o >>= 1) {
        s  += __shfl_xor_sync(0xffffffffu, s,  o);
        s2 += __shfl_xor_sync(0xffffffffu, s2, o);
    }
    float mean = s * (1.0f / E_);
    float rstd = rsqrtf(s2 * (1.0f / E_) - mean*mean + 1e-5f);

    uint4* xw = reinterpret_cast<uint4*>(Xf + (size_t)row * E_);
    #pragma unroll
    for (int j = 0; j < 2; j++) {
        int base = (lane + 32*j) * 8;
        uint4 o;
        __half2* oh = reinterpret_cast<__half2*>(&o);
        #pragma unroll
        for (int q = 0; q < 4; q++) {
            float2 wv = *reinterpret_cast<const float2*>(w + base + 2*q);
            float2 bv = *reinterpret_cast<const float2*>(b + base + 2*q);
            float o0 = (vals[j*8 + 2*q]     - mean) * rstd * wv.x + bv.x;
            float o1 = (vals[j*8 + 2*q + 1] - mean) * rstd * wv.y + bv.y;
            __half2 h; h.x = __float2half_rn(o0); h.y = __float2half_rn(o1);
            oh[q] = h;
        }
        xw[lane + 32*j] = o;
    }
}

// ---------------- discriminator head (vectorized) ----------------
__global__ void disc_kernel(const float* __restrict__ bert,
                            const __half* __restrict__ posf,
                            const float* __restrict__ wd,
                            const float* __restrict__ bd,
                            float* __restrict__ out, int ntok) {
    int n = (blockIdx.x * blockDim.x + threadIdx.x) >> 5;
    int lane = threadIdx.x & 31;
    if (n >= ntok) return;
    float acc = 0.0f;
    const float4* br4 = reinterpret_cast<const float4*>(bert + (size_t)n * F_);
    const float4* wd4 = reinterpret_cast<const float4*>(wd);
    #pragma unroll
    for (int j = 0; j < 6; j++) {
        int idx = lane + 32*j;
        float4 v = br4[idx];
        float4 wv = wd4[idx];
        acc += v.x*wv.x + v.y*wv.y + v.z*wv.z + v.w*wv.w;
    }
    const uint4* pr4 = reinterpret_cast<const uint4*>(posf + (size_t)n * F_);
    #pragma unroll
    for (int j = 0; j < 3; j++) {
        int idx = lane + 32*j;
        uint4 u = pr4[idx];
        const __half2* ph = reinterpret_cast<const __half2*>(&u);
        const float* wp = wd + F_ + idx*8;
        #pragma unroll
        for (int q = 0; q < 4; q++) {
            float2 f = __half22float2(ph[q]);
            acc += f.x * wp[2*q] + f.y * wp[2*q + 1];
        }
    }
    #pragma unroll
    for (int o = 16; o; o >>= 1) acc += __shfl_xor_sync(0xffffffffu, acc, o);
    if (lane == 0) out[n] = 1.0f / (1.0f + expf(-(acc + bd[0])));
}

// ---------------- host orchestration ----------------
static inline int cdiv(int a, int b) { return (a + b - 1) / b; }

extern "C" void kernel_launch(void* const* d_in, const int* in_sizes, int n_in,
                              void* d_out, int out_size) {
    const int*   pos1  = (const int*)d_in[0];
    const int*   pos2  = (const int*)d_in[1];
    const float* bert  = (const float*)d_in[2];
    const float* fbase = (const float*)d_in[3];
    const float* emb   = (const float*)d_in[4];
    const float* wqkv  = (const float*)d_in[5];
    const float* bqkv  = (const float*)d_in[6];
    const float* wo    = (const float*)d_in[7];
    const float* bo    = (const float*)d_in[8];
    const float* ln1w  = (const float*)d_in[9];
    const float* ln1b  = (const float*)d_in[10];
    const float* ln2w  = (const float*)d_in[11];
    const float* ln2b  = (const float*)d_in[12];
    const float* w1    = (const float*)d_in[13];
    const float* b1    = (const float*)d_in[14];
    const float* w2    = (const float*)d_in[15];
    const float* b2    = (const float*)d_in[16];
    const float* wm    = (const float*)d_in[17];
    const float* wd    = (const float*)d_in[18];
    const float* bd    = (const float*)d_in[19];
    float* out = (float*)d_out;

    float *PE; int* SPAN;
    __half *Xf, *Yh, *QKVf, *CXf, *Hf, *POSFh, *WQf, *WOf, *W1f, *W2f, *WMf;
    cudaGetSymbolAddress((void**)&PE,    d_PE);
    cudaGetSymbolAddress((void**)&SPAN,  d_SPAN);
    cudaGetSymbolAddress((void**)&Xf,    d_Xf);
    cudaGetSymbolAddress((void**)&Yh,    d_Yh);
    cudaGetSymbolAddress((void**)&QKVf,  d_QKVf);
    cudaGetSymbolAddress((void**)&CXf,   d_CXf);
    cudaGetSymbolAddress((void**)&Hf,    d_Hf);
    cudaGetSymbolAddress((void**)&POSFh, d_POSFh);
    cudaGetSymbolAddress((void**)&WQf,   d_WQf);
    cudaGetSymbolAddress((void**)&WOf,   d_WOf);
    cudaGetSymbolAddress((void**)&W1f,   d_W1f);
    cudaGetSymbolAddress((void**)&W2f,   d_W2f);
    cudaGetSymbolAddress((void**)&WMf,   d_WMf);

    cudaFuncSetAttribute(gemm_tc, cudaFuncAttributeMaxDynamicSharedMemorySize, SMEM_GEMM);

    // launch 0: convert wqkv + wo
    {
        int n1 = 2*3*E_*E_/4, n2 = 2*E_*E_/4;
        cvt2_kernel<<<cdiv(n1+n2,256),256>>>(wqkv, WQf, n1, wo, WOf, n2);
    }
    // launch 1: fused span + PE
    spanpe_kernel<<<32 + cdiv(M_*E_, 512), 512>>>(pos1, SPAN, PE);
    // launch 2: build x (fp16 only)
    build_x_kernel<<<NTOK, 512>>>(pos2, fbase, emb, SPAN, PE, Xf);

    const int MY = cdiv(NTOK, BM);   // 129
    bool cvt3_done = false;

    for (int l = 0; l < 2; l++) {
        const size_t oq = (size_t)l * 3*E_ * E_;
        const size_t oo = (size_t)l * E_ * E_;
        const size_t o1 = (size_t)l * DFF_ * E_;
        const size_t o2 = (size_t)l * E_ * DFF_;

        { dim3 g(3*E_/BN, MY);   // QKV (fp16 out) — launch 3, layer 0
          gemm_tc<<<g, NTHR_G, SMEM_GEMM>>>(Xf, WQf+oq,
              nullptr, QKVf, NTOK, 3*E_, E_, bqkv + l*3*E_, 0); }

        if (!cvt3_done) {
            int n1 = 2*DFF_*E_/4, n2 = 2*E_*DFF_/4, n3 = F_*E_/4;
            cvt3_kernel<<<cdiv(n1+n2+n3,256),256>>>(w1, W1f, n1,
                                                    w2, W2f, n2,
                                                    wm, WMf, n3);
            cvt3_done = true;
        }

        attn_kernel<<<S_*NHEAD_, 256>>>(QKVf, CXf);

        { dim3 g(E_/BN, MY);     // Wo -> fp16 Y
          gemm_tc<<<g, NTHR_G, SMEM_GEMM>>>(CXf, WOf+oo,
              nullptr, Yh, NTOK, E_, E_, bo + l*E_, 0); }

        add_ln_kernel<<<NTOK/8, 256>>>(Xf, Yh, ln1w + l*E_, ln1b + l*E_);

        { dim3 g(DFF_/BN, MY);   // FFN1 -> f16 H
          gemm_tc<<<g, NTHR_G, SMEM_GEMM>>>(Xf, W1f+o1,
              nullptr, Hf, NTOK, DFF_, E_, b1 + l*DFF_, 1); }

        { dim3 g(E_/BN, MY);     // FFN2 -> fp16 Y
          gemm_tc<<<g, NTHR_G, SMEM_GEMM>>>(Hf, W2f+o2,
              nullptr, Yh, NTOK, E_, DFF_, b2 + l*E_, 0); }

        add_ln_kernel<<<NTOK/8, 256>>>(Xf, Yh, ln2w + l*E_, ln2b + l*E_);
    }

    { dim3 g(F_/BN, MY);         // pos_feature = tanh(X @ wm^T), fp16 out
      gemm_tc<<<g, NTHR_G, SMEM_GEMM>>>(Xf, WMf,
          nullptr, POSFh, NTOK, F_, E_, nullptr, 2); }

    disc_kernel<<<cdiv(NTOK*32, 256), 256>>>(bert, POSFh, wd, bd, out, NTOK);
}

// round 15
// speedup vs baseline: 1.0567x; 1.0567x over previous
#include <cuda_runtime.h>
#include <cuda_fp16.h>
#include <math.h>
#include <stdint.h>

// ---------------- problem constants ----------------
#define B_    32
#define M_    512
#define E_    512
#define S_    513
#define NTOK  (B_*S_)          // 16416
#define NHEAD_ 8
#define DH_   64
#define DFF_  2048
#define F_    768

// ---------------- scratch ----------------
__device__ float d_PE[M_*E_];
__device__ int   d_SPAN[B_*M_];

// ---------------- fp16 activation / weight buffers ----------------
__device__ __align__(16) __half d_Xf   [(size_t)NTOK*E_];
__device__ __align__(16) __half d_Yh   [(size_t)NTOK*E_];
__device__ __align__(16) __half d_QKVf [(size_t)NTOK*3*E_];
__device__ __align__(16) __half d_CXf  [(size_t)NTOK*E_];
__device__ __align__(16) __half d_Hf   [(size_t)NTOK*DFF_];
__device__ __align__(16) __half d_POSFh[(size_t)NTOK*F_];
__device__ __align__(16) __half d_WQf  [(size_t)2*3*E_*E_];
__device__ __align__(16) __half d_WOf  [(size_t)2*E_*E_];
__device__ __align__(16) __half d_W1f  [(size_t)2*DFF_*E_];
__device__ __align__(16) __half d_W2f  [(size_t)2*E_*DFF_];
__device__ __align__(16) __half d_WMf  [(size_t)F_*E_];

// ================= fp16 tensor-core GEMM (BK=64, 2 CTAs/SM) ========
#define BM 128
#define BN 128
#define BK 64
#define PADB 144
#define A_ARR (128*PADB)
#define B_ARR (128*PADB)
#define STAGE (A_ARR + B_ARR)
#define NSTAGE 3
#define SMEM_GEMM (NSTAGE*STAGE)
#define NTHR_G 256

__device__ __forceinline__ uint32_t smem_u32(const void* p) {
    uint32_t a;
    asm("{ .reg .u64 t; cvta.to.shared.u64 t, %1; cvt.u32.u64 %0, t; }"
        : "=r"(a) : "l"(p));
    return a;
}
__device__ __forceinline__ void ldsm4(uint32_t* r, uint32_t addr) {
    asm volatile("ldmatrix.sync.aligned.m8n8.x4.shared.b16 {%0,%1,%2,%3}, [%4];"
        : "=r"(r[0]), "=r"(r[1]), "=r"(r[2]), "=r"(r[3]) : "r"(addr));
}
__device__ __forceinline__ void mma16816(float* c, const uint32_t* a, const uint32_t* b) {
    asm volatile(
        "mma.sync.aligned.m16n8k16.row.col.f32.f16.f16.f32 "
        "{%0,%1,%2,%3}, {%4,%5,%6,%7}, {%8,%9}, {%0,%1,%2,%3};"
        : "+f"(c[0]), "+f"(c[1]), "+f"(c[2]), "+f"(c[3])
        : "r"(a[0]), "r"(a[1]), "r"(a[2]), "r"(a[3]), "r"(b[0]), "r"(b[1]));
}
__device__ __forceinline__ void cpa16(uint32_t dst, const void* src, int srcsize) {
    asm volatile("cp.async.cg.shared.global [%0], [%1], 16, %2;"
                 :: "r"(dst), "l"(src), "r"(srcsize));
}

__device__ __forceinline__ void load_stage(
    uint32_t st,
    const __half* __restrict__ Af, const __half* __restrict__ Bf,
    int tile_m, int tile_n, int Mdim, int Kdim, int kc, int tid)
{
    const int k0 = kc * BK;
    #pragma unroll
    for (int i = 0; i < 4; i++) {
        int id = tid + NTHR_G*i;
        int row = id >> 3, c = id & 7;
        const __half* src = Af + (size_t)(tile_m + row) * Kdim + k0 + c*8;
        cpa16(st + row*PADB + c*16, src, (tile_m + row) < Mdim ? 16 : 0);
    }
    #pragma unroll
    for (int i = 0; i < 4; i++) {
        int id = tid + NTHR_G*i;
        int row = id >> 3, c = id & 7;
        const __half* src = Bf + (size_t)(tile_n + row) * Kdim + k0 + c*8;
        cpa16(st + A_ARR + row*PADB + c*16, src, 16);
    }
    asm volatile("cp.async.commit_group;" ::: "memory");
}

__global__ __launch_bounds__(NTHR_G, 2)
void gemm_tc(const __half* __restrict__ Af, const __half* __restrict__ Bf,
             __half* __restrict__ Chalf,
             int Mdim, int Ndim, int Kdim,
             const float* __restrict__ bias, int act)
{
    extern __shared__ __align__(16) char smem[];
    const uint32_t sb = smem_u32(smem);
    const int tid    = threadIdx.x;
    const int tile_m = blockIdx.y * BM;
    const int tile_n = blockIdx.x * BN;
    const int warp = tid >> 5, lane = tid & 31;
    const int wm2 = warp >> 2, wn4 = warp & 3;

    float acc[4][4][4];
    #pragma unroll
    for (int a = 0; a < 4; a++)
        #pragma unroll
        for (int b = 0; b < 4; b++)
            #pragma unroll
            for (int q = 0; q < 4; q++) acc[a][b][q] = 0.0f;

    const int nst = Kdim / BK;
    load_stage(sb,         Af, Bf, tile_m, tile_n, Mdim, Kdim, 0, tid);
    load_stage(sb + STAGE, Af, Bf, tile_m, tile_n, Mdim, Kdim, 1, tid);

    const uint32_t a_off = (uint32_t)(wm2*64 + (lane & 7) + ((lane >> 3) & 1) * 8) * PADB
                         + ((lane >> 4) * 16);
    const uint32_t b_off = (uint32_t)(wn4*32 + (lane & 7) + ((lane >> 4) & 1) * 8) * PADB
                         + (((lane >> 3) & 1) * 16);

    for (int s = 0; s < nst; s++) {
        if (s + 1 < nst) asm volatile("cp.async.wait_group 1;" ::: "memory");
        else             asm volatile("cp.async.wait_group 0;" ::: "memory");
        __syncthreads();
        if (s + 2 < nst)
            load_stage(sb + ((s + 2) % NSTAGE) * STAGE, Af, Bf,
                       tile_m, tile_n, Mdim, Kdim, s + 2, tid);
        const uint32_t st = sb + (s % NSTAGE) * STAGE;

        #pragma unroll
        for (int ks = 0; ks < 4; ks++) {
            uint32_t ah[4][4], bh[4][2];
            #pragma unroll
            for (int mi = 0; mi < 4; mi++)
                ldsm4(ah[mi], st + a_off + mi * (16 * PADB) + ks * 32);
            #pragma unroll
            for (int p = 0; p < 2; p++) {
                uint32_t r[4];
                ldsm4(r, st + A_ARR + b_off + p * (16 * PADB) + ks * 32);
                bh[2*p][0] = r[0]; bh[2*p][1] = r[1];
                bh[2*p+1][0] = r[2]; bh[2*p+1][1] = r[3];
            }
            #pragma unroll
            for (int mi = 0; mi < 4; mi++)
                #pragma unroll
                for (int ni = 0; ni < 4; ni++)
                    mma16816(acc[mi][ni], ah[mi], bh[ni]);
        }
    }

    // ---- epilogue (fp16 out only) ----
    const int er = lane >> 2;
    const int ec = (lane & 3) * 2;
    #pragma unroll
    for (int mi = 0; mi < 4; mi++) {
        const int gm0 = tile_m + wm2*64 + mi*16 + er;
        #pragma unroll
        for (int ni = 0; ni < 4; ni++) {
            const int gn = tile_n + wn4*32 + ni*8 + ec;
            float bx = 0.f, by = 0.f;
            if (bias) { float2 bb = *reinterpret_cast<const float2*>(bias + gn);
                        bx = bb.x; by = bb.y; }
            float v0 = acc[mi][ni][0] + bx, v1 = acc[mi][ni][1] + by;
            float v2 = acc[mi][ni][2] + bx, v3 = acc[mi][ni][3] + by;
            if (act == 1) {
                v0 = fmaxf(v0, 0.f); v1 = fmaxf(v1, 0.f);
                v2 = fmaxf(v2, 0.f); v3 = fmaxf(v3, 0.f);
            } else if (act == 2) {
                v0 = tanhf(v0); v1 = tanhf(v1); v2 = tanhf(v2); v3 = tanhf(v3);
            }
            if (gm0 < Mdim) {
                __half2 h; h.x = __float2half_rn(v0); h.y = __float2half_rn(v1);
                *reinterpret_cast<__half2*>(Chalf + (size_t)gm0 * Ndim + gn) = h;
            }
            if (gm0 + 8 < Mdim) {
                __half2 h; h.x = __float2half_rn(v2); h.y = __float2half_rn(v3);
                *reinterpret_cast<__half2*>(Chalf + (size_t)(gm0+8) * Ndim + gn) = h;
            }
        }
    }
}

// ---------------- fp32 -> fp16 convert: all 5 weights, one launch ----------------
__device__ __forceinline__ void cvt_one(const float* in, __half* o, int i) {
    float4 v = *reinterpret_cast<const float4*>(in + (size_t)i * 4);
    __half2 h0, h1;
    h0.x = __float2half_rn(v.x); h0.y = __float2half_rn(v.y);
    h1.x = __float2half_rn(v.z); h1.y = __float2half_rn(v.w);
    uint2 u;
    u.x = *reinterpret_cast<uint32_t*>(&h0);
    u.y = *reinterpret_cast<uint32_t*>(&h1);
    *reinterpret_cast<uint2*>(o + (size_t)i * 4) = u;
}
__global__ void cvt5_kernel(const float* i1, __half* o1, int n1,
                            const float* i2, __half* o2, int n2,
                            const float* i3, __half* o3, int n3,
                            const float* i4, __half* o4, int n4,
                            const float* i5, __half* o5, int n5) {
    int i = blockIdx.x * blockDim.x + threadIdx.x;
    if (i < n1) { cvt_one(i1, o1, i); return; }
    i -= n1;
    if (i < n2) { cvt_one(i2, o2, i); return; }
    i -= n2;
    if (i < n3) { cvt_one(i3, o3, i); return; }
    i -= n3;
    if (i < n4) { cvt_one(i4, o4, i); return; }
    i -= n4;
    if (i < n5) cvt_one(i5, o5, i);
}

// ---------------- fused span-id + PE table ----------------
__global__ void spanpe_kernel(const int* __restrict__ pos1, int* __restrict__ span,
                              float* __restrict__ pe) {
    if (blockIdx.x < 32) {
        int b = blockIdx.x;
        int j = threadIdx.x;
        __shared__ int firstZero;
        span[b*M_ + j] = -1;
        if (j == 0) firstZero = M_;
        __syncthreads();
        int endv = pos1[((size_t)b*M_ + j)*2 + 1];
        if (endv == 0) atomicMin(&firstZero, j);
        __syncthreads();
        if (j < firstZero) {
            int st = pos1[((size_t)b*M_ + j)*2];
            int en = endv; if (en > M_) en = M_;
            for (int k = st; k < en; k++)
                atomicMax(&span[b*M_ + k], j);
        }
    } else {
        int idx = (blockIdx.x - 32) * 512 + threadIdx.x;
        if (idx >= M_ * E_) return;
        int pos = idx / E_, i = idx % E_;
        double e2  = (double)((i / 2) * 2);
        double ang = (double)pos / pow(10000.0, e2 / (double)E_);
        pe[idx] = (float)((i % 2 == 0) ? sin(ang) : cos(ang));
    }
}

// ---------------- build x: warp per row, vectorized ----------------
__global__ void build_x_kernel(const int* __restrict__ pos2,
                               const float* __restrict__ fbase,
                               const float* __restrict__ emb,
                               const int* __restrict__ span,
                               const float* __restrict__ pe,
                               __half* __restrict__ Xf) {
    int row  = blockIdx.x * 8 + (threadIdx.x >> 5);   // token index
    int lane = threadIdx.x & 31;
    int b = row / S_, s = row % S_;

    const float* srcA = nullptr;   // primary source
    const float* srcB = nullptr;   // optional additive source (PE)
    if (s == 0) {
        srcA = emb + (size_t)1 * E_;
    } else {
        int k = s - 1;
        int sid = span[b*M_ + k];
        if (sid >= 0) {
            int p = pos2[b*M_ + sid];
            srcA = (p == 0) ? nullptr : emb + (size_t)p * E_;
            srcB = pe + (size_t)sid * E_;
        } else {
            srcA = fbase + ((size_t)b*M_ + k) * E_;
        }
    }

    __half* dst = Xf + (size_t)row * E_;
    #pragma unroll
    for (int j = 0; j < 4; j++) {              // 4 float4 = 16 floats per lane
        int i4 = lane + 32*j;                   // float4 index (128 per row)
        float4 v = srcA ? reinterpret_cast<const float4*>(srcA)[i4]
                        : make_float4(0.f, 0.f, 0.f, 0.f);
        if (srcB) {
            float4 p4 = reinterpret_cast<const float4*>(srcB)[i4];
            v.x += p4.x; v.y += p4.y; v.z += p4.z; v.w += p4.w;
        }
        __half2 h0, h1;
        h0.x = __float2half_rn(v.x); h0.y = __float2half_rn(v.y);
        h1.x = __float2half_rn(v.z); h1.y = __float2half_rn(v.w);
        uint2 u;
        u.x = *reinterpret_cast<uint32_t*>(&h0);
        u.y = *reinterpret_cast<uint32_t*>(&h1);
        *reinterpret_cast<uint2*>(dst + 4*i4) = u;
    }
}

// ---------------- fused attention over the B axis ----------------
__global__ void attn_kernel(const __half* __restrict__ QKV,
                            __half* __restrict__ CXf) {
    int z = blockIdx.x;
    int s = z / NHEAD_, h = z % NHEAD_;
    __shared__ float q[B_][DH_];
    __shared__ float k[B_][DH_ + 1];   // pad: conflict-free scores
    __shared__ float v[B_][DH_];
    __shared__ float sc[B_][B_ + 1];

    const __half* base = QKV + (size_t)s * 3*E_ + (size_t)h * DH_;
    int t = threadIdx.x;

    for (int i = t; i < B_*(DH_/2); i += 256) {
        int b = i / (DH_/2), d2 = i % (DH_/2);
        size_t off = (size_t)b * S_ * 3*E_ + 2*d2;
        __half2 hq = *reinterpret_cast<const __half2*>(base + off);
        __half2 hk = *reinterpret_cast<const __half2*>(base + off + E_);
        __half2 hv = *reinterpret_cast<const __half2*>(base + off + 2*E_);
        q[b][2*d2] = __half2float(hq.x); q[b][2*d2+1] = __half2float(hq.y);
        k[b][2*d2] = __half2float(hk.x); k[b][2*d2+1] = __half2float(hk.y);
        v[b][2*d2] = __half2float(hv.x); v[b][2*d2+1] = __half2float(hv.y);
    }
    __syncthreads();

    for (int i = t; i < B_*B_; i += 256) {
        int l = i / B_, m = i % B_;
        float acc = 0.0f;
        #pragma unroll
        for (int d = 0; d < DH_; d++) acc += q[l][d] * k[m][d];
        sc[l][m] = acc * 0.125f;
    }
    __syncthreads();

    int warp = t >> 5, lane = t & 31;
    for (int l = warp; l < B_; l += 8) {
        float val = sc[l][lane];
        float mx = val;
        #pragma unroll
        for (int o = 16; o; o >>= 1) mx = fmaxf(mx, __shfl_xor_sync(0xffffffffu, mx, o));
        float e = expf(val - mx);
        float sum = e;
        #pragma unroll
        for (int o = 16; o; o >>= 1) sum += __shfl_xor_sync(0xffffffffu, sum, o);
        sc[l][lane] = e / sum;
    }
    __syncthreads();

    for (int i = t; i < B_*DH_; i += 256) {
        int l = i / DH_, d = i % DH_;
        float acc = 0.0f;
        #pragma unroll
        for (int m = 0; m < B_; m++) acc += sc[l][m] * v[m][d];
        CXf[((size_t)l * S_ + s) * E_ + (size_t)h * DH_ + d] = __float2half_rn(acc);
    }
}

// ---------------- residual add + layernorm: all-fp16 IO, warp per row ------
__global__ void add_ln_kernel(__half* __restrict__ Xf, const __half* __restrict__ Yh,
                              const float* __restrict__ w, const float* __restrict__ b) {
    int row  = blockIdx.x * 8 + (threadIdx.x >> 5);
    int lane = threadIdx.x & 31;
    const uint4* xr = reinterpret_cast<const uint4*>(Xf + (size_t)row * E_);
    const uint4* yr = reinterpret_cast<const uint4*>(Yh + (size_t)row * E_);

    float vals[16];
    float s = 0.f, s2 = 0.f;
    #pragma unroll
    for (int j = 0; j < 2; j++) {
        uint4 xa = xr[lane + 32*j];
        uint4 ya = yr[lane + 32*j];
        const __half2* xh = reinterpret_cast<const __half2*>(&xa);
        const __half2* yh = reinterpret_cast<const __half2*>(&ya);
        #pragma unroll
        for (int q = 0; q < 4; q++) {
            float2 fx = __half22float2(xh[q]);
            float2 fy = __half22float2(yh[q]);
            float a0 = fx.x + fy.x, a1 = fx.y + fy.y;
            vals[j*8 + 2*q]     = a0;
            vals[j*8 + 2*q + 1] = a1;
            s  += a0 + a1;
            s2 += a0*a0 + a1*a1;
        }
    }
    #pragma unroll
    for (int o = 16; o; o >>= 1) {
        s  += __shfl_xor_sync(0xffffffffu, s,  o);
        s2 += __shfl_xor_sync(0xffffffffu, s2, o);
    }
    float mean = s * (1.0f / E_);
    float rstd = rsqrtf(s2 * (1.0f / E_) - mean*mean + 1e-5f);

    uint4* xw = reinterpret_cast<uint4*>(Xf + (size_t)row * E_);
    #pragma unroll
    for (int j = 0; j < 2; j++) {
        int base = (lane + 32*j) * 8;
        uint4 o;
        __half2* oh = reinterpret_cast<__half2*>(&o);
        #pragma unroll
        for (int q = 0; q < 4; q++) {
            float2 wv = *reinterpret_cast<const float2*>(w + base + 2*q);
            float2 bv = *reinterpret_cast<const float2*>(b + base + 2*q);
            float o0 = (vals[j*8 + 2*q]     - mean) * rstd * wv.x + bv.x;
            float o1 = (vals[j*8 + 2*q + 1] - mean) * rstd * wv.y + bv.y;
            __half2 h; h.x = __float2half_rn(o0); h.y = __float2half_rn(o1);
            oh[q] = h;
        }
        xw[lane + 32*j] = o;
    }
}

// ---------------- discriminator head (vectorized) ----------------
__global__ void disc_kernel(const float* __restrict__ bert,
                            const __half* __restrict__ posf,
                            const float* __restrict__ wd,
                            const float* __restrict__ bd,
                            float* __restrict__ out, int ntok) {
    int n = (blockIdx.x * blockDim.x + threadIdx.x) >> 5;
    int lane = threadIdx.x & 31;
    if (n >= ntok) return;
    float acc = 0.0f;
    const float4* br4 = reinterpret_cast<const float4*>(bert + (size_t)n * F_);
    const float4* wd4 = reinterpret_cast<const float4*>(wd);
    #pragma unroll
    for (int j = 0; j < 6; j++) {
        int idx = lane + 32*j;
        float4 v = br4[idx];
        float4 wv = wd4[idx];
        acc += v.x*wv.x + v.y*wv.y + v.z*wv.z + v.w*wv.w;
    }
    const uint4* pr4 = reinterpret_cast<const uint4*>(posf + (size_t)n * F_);
    #pragma unroll
    for (int j = 0; j < 3; j++) {
        int idx = lane + 32*j;
        uint4 u = pr4[idx];
        const __half2* ph = reinterpret_cast<const __half2*>(&u);
        const float* wp = wd + F_ + idx*8;
        #pragma unroll
        for (int q = 0; q < 4; q++) {
            float2 f = __half22float2(ph[q]);
            acc += f.x * wp[2*q] + f.y * wp[2*q + 1];
        }
    }
    #pragma unroll
    for (int o = 16; o; o >>= 1) acc += __shfl_xor_sync(0xffffffffu, acc, o);
    if (lane == 0) out[n] = 1.0f / (1.0f + expf(-(acc + bd[0])));
}

// ---------------- host orchestration ----------------
static inline int cdiv(int a, int b) { return (a + b - 1) / b; }

extern "C" void kernel_launch(void* const* d_in, const int* in_sizes, int n_in,
                              void* d_out, int out_size) {
    const int*   pos1  = (const int*)d_in[0];
    const int*   pos2  = (const int*)d_in[1];
    const float* bert  = (const float*)d_in[2];
    const float* fbase = (const float*)d_in[3];
    const float* emb   = (const float*)d_in[4];
    const float* wqkv  = (const float*)d_in[5];
    const float* bqkv  = (const float*)d_in[6];
    const float* wo    = (const float*)d_in[7];
    const float* bo    = (const float*)d_in[8];
    const float* ln1w  = (const float*)d_in[9];
    const float* ln1b  = (const float*)d_in[10];
    const float* ln2w  = (const float*)d_in[11];
    const float* ln2b  = (const float*)d_in[12];
    const float* w1    = (const float*)d_in[13];
    const float* b1    = (const float*)d_in[14];
    const float* w2    = (const float*)d_in[15];
    const float* b2    = (const float*)d_in[16];
    const float* wm    = (const float*)d_in[17];
    const float* wd    = (const float*)d_in[18];
    const float* bd    = (const float*)d_in[19];
    float* out = (float*)d_out;

    float *PE; int* SPAN;
    __half *Xf, *Yh, *QKVf, *CXf, *Hf, *POSFh, *WQf, *WOf, *W1f, *W2f, *WMf;
    cudaGetSymbolAddress((void**)&PE,    d_PE);
    cudaGetSymbolAddress((void**)&SPAN,  d_SPAN);
    cudaGetSymbolAddress((void**)&Xf,    d_Xf);
    cudaGetSymbolAddress((void**)&Yh,    d_Yh);
    cudaGetSymbolAddress((void**)&QKVf,  d_QKVf);
    cudaGetSymbolAddress((void**)&CXf,   d_CXf);
    cudaGetSymbolAddress((void**)&Hf,    d_Hf);
    cudaGetSymbolAddress((void**)&POSFh, d_POSFh);
    cudaGetSymbolAddress((void**)&WQf,   d_WQf);
    cudaGetSymbolAddress((void**)&WOf,   d_WOf);
    cudaGetSymbolAddress((void**)&W1f,   d_W1f);
    cudaGetSymbolAddress((void**)&W2f,   d_W2f);
    cudaGetSymbolAddress((void**)&WMf,   d_WMf);

    cudaFuncSetAttribute(gemm_tc, cudaFuncAttributeMaxDynamicSharedMemorySize, SMEM_GEMM);

    // launch 0: convert ALL weights (one kernel)
    {
        int n1 = 2*3*E_*E_/4, n2 = 2*E_*E_/4;
        int n3 = 2*DFF_*E_/4, n4 = 2*E_*DFF_/4, n5 = F_*E_/4;
        cvt5_kernel<<<cdiv(n1+n2+n3+n4+n5, 256), 256>>>(
            wqkv, WQf, n1, wo, WOf, n2, w1, W1f, n3, w2, W2f, n4, wm, WMf, n5);
    }
    // launch 1: fused span + PE
    spanpe_kernel<<<32 + cdiv(M_*E_, 512), 512>>>(pos1, SPAN, PE);
    // launch 2: build x (warp per row)
    build_x_kernel<<<NTOK/8, 256>>>(pos2, fbase, emb, SPAN, PE, Xf);

    const int MY = cdiv(NTOK, BM);   // 129

    for (int l = 0; l < 2; l++) {
        const size_t oq = (size_t)l * 3*E_ * E_;
        const size_t oo = (size_t)l * E_ * E_;
        const size_t o1 = (size_t)l * DFF_ * E_;
        const size_t o2 = (size_t)l * E_ * DFF_;

        { dim3 g(3*E_/BN, MY);   // QKV -> fp16 (launch 3, layer 0)
          gemm_tc<<<g, NTHR_G, SMEM_GEMM>>>(Xf, WQf+oq,
              QKVf, NTOK, 3*E_, E_, bqkv + l*3*E_, 0); }

        attn_kernel<<<S_*NHEAD_, 256>>>(QKVf, CXf);

        { dim3 g(E_/BN, MY);     // Wo -> fp16 Y
          gemm_tc<<<g, NTHR_G, SMEM_GEMM>>>(CXf, WOf+oo,
              Yh, NTOK, E_, E_, bo + l*E_, 0); }

        add_ln_kernel<<<NTOK/8, 256>>>(Xf, Yh, ln1w + l*E_, ln1b + l*E_);

        { dim3 g(DFF_/BN, MY);   // FFN1 -> f16 H
          gemm_tc<<<g, NTHR_G, SMEM_GEMM>>>(Xf, W1f+o1,
              Hf, NTOK, DFF_, E_, b1 + l*DFF_, 1); }

        { dim3 g(E_/BN, MY);     // FFN2 -> fp16 Y
          gemm_tc<<<g, NTHR_G, SMEM_GEMM>>>(Hf, W2f+o2,
              Yh, NTOK, E_, DFF_, b2 + l*E_, 0); }

        add_ln_kernel<<<NTOK/8, 256>>>(Xf, Yh, ln2w + l*E_, ln2b + l*E_);
    }

    { dim3 g(F_/BN, MY);         // pos_feature = tanh(X @ wm^T), fp16 out
      gemm_tc<<<g, NTHR_G, SMEM_GEMM>>>(Xf, WMf,
          POSFh, NTOK, F_, E_, nullptr, 2); }

    disc_kernel<<<cdiv(NTOK*32, 256), 256>>>(bert, POSFh, wd, bd, out, NTOK);
}

// round 16
// speedup vs baseline: 1.0703x; 1.0129x over previous
#include <cuda_runtime.h>
#include <cuda_fp16.h>
#include <math.h>
#include <stdint.h>

// ---------------- problem constants ----------------
#define B_    32
#define M_    512
#define E_    512
#define S_    513
#define NTOK  (B_*S_)          // 16416
#define NHEAD_ 8
#define DH_   64
#define DFF_  2048
#define F_    768

// ---------------- scratch ----------------
__device__ float d_PE[M_*E_];
__device__ int   d_SPAN[B_*M_];

// ---------------- fp16 activation / weight buffers ----------------
__device__ __align__(16) __half d_Xf   [(size_t)NTOK*E_];
__device__ __align__(16) __half d_Yh   [(size_t)NTOK*E_];
__device__ __align__(16) __half d_QKVf [(size_t)NTOK*3*E_];
__device__ __align__(16) __half d_CXf  [(size_t)NTOK*E_];
__device__ __align__(16) __half d_Hf   [(size_t)NTOK*DFF_];
__device__ __align__(16) __half d_POSFh[(size_t)NTOK*F_];
__device__ __align__(16) __half d_WQf  [(size_t)2*3*E_*E_];
__device__ __align__(16) __half d_WOf  [(size_t)2*E_*E_];
__device__ __align__(16) __half d_W1f  [(size_t)2*DFF_*E_];
__device__ __align__(16) __half d_W2f  [(size_t)2*E_*DFF_];
__device__ __align__(16) __half d_WMf  [(size_t)F_*E_];

// ================= fp16 tensor-core GEMM (BK=64, 2 CTAs/SM) ========
#define BM 128
#define BN 128
#define BK 64
#define PADB 144
#define A_ARR (128*PADB)
#define B_ARR (128*PADB)
#define STAGE (A_ARR + B_ARR)
#define NSTAGE 3
#define SMEM_GEMM (NSTAGE*STAGE)
#define NTHR_G 256

__device__ __forceinline__ uint32_t smem_u32(const void* p) {
    uint32_t a;
    asm("{ .reg .u64 t; cvta.to.shared.u64 t, %1; cvt.u32.u64 %0, t; }"
        : "=r"(a) : "l"(p));
    return a;
}
__device__ __forceinline__ void ldsm4(uint32_t* r, uint32_t addr) {
    asm volatile("ldmatrix.sync.aligned.m8n8.x4.shared.b16 {%0,%1,%2,%3}, [%4];"
        : "=r"(r[0]), "=r"(r[1]), "=r"(r[2]), "=r"(r[3]) : "r"(addr));
}
__device__ __forceinline__ void mma16816(float* c, const uint32_t* a, const uint32_t* b) {
    asm volatile(
        "mma.sync.aligned.m16n8k16.row.col.f32.f16.f16.f32 "
        "{%0,%1,%2,%3}, {%4,%5,%6,%7}, {%8,%9}, {%0,%1,%2,%3};"
        : "+f"(c[0]), "+f"(c[1]), "+f"(c[2]), "+f"(c[3])
        : "r"(a[0]), "r"(a[1]), "r"(a[2]), "r"(a[3]), "r"(b[0]), "r"(b[1]));
}
__device__ __forceinline__ void cpa16(uint32_t dst, const void* src, int srcsize) {
    asm volatile("cp.async.cg.shared.global [%0], [%1], 16, %2;"
                 :: "r"(dst), "l"(src), "r"(srcsize));
}

__device__ __forceinline__ void load_stage(
    uint32_t st,
    const __half* __restrict__ Af, const __half* __restrict__ Bf,
    int tile_m, int tile_n, int Mdim, int Kdim, int kc, int tid)
{
    const int k0 = kc * BK;
    #pragma unroll
    for (int i = 0; i < 4; i++) {
        int id = tid + NTHR_G*i;
        int row = id >> 3, c = id & 7;
        const __half* src = Af + (size_t)(tile_m + row) * Kdim + k0 + c*8;
        cpa16(st + row*PADB + c*16, src, (tile_m + row) < Mdim ? 16 : 0);
    }
    #pragma unroll
    for (int i = 0; i < 4; i++) {
        int id = tid + NTHR_G*i;
        int row = id >> 3, c = id & 7;
        const __half* src = Bf + (size_t)(tile_n + row) * Kdim + k0 + c*8;
        cpa16(st + A_ARR + row*PADB + c*16, src, 16);
    }
    asm volatile("cp.async.commit_group;" ::: "memory");
}

__global__ __launch_bounds__(NTHR_G, 2)
void gemm_tc(const __half* __restrict__ Af, const __half* __restrict__ Bf,
             __half* __restrict__ Chalf,
             int Mdim, int Ndim, int Kdim,
             const float* __restrict__ bias, int act)
{
    extern __shared__ __align__(16) char smem[];
    const uint32_t sb = smem_u32(smem);
    const int tid    = threadIdx.x;
    const int tile_m = blockIdx.y * BM;
    const int tile_n = blockIdx.x * BN;
    const int warp = tid >> 5, lane = tid & 31;
    const int wm2 = warp >> 2, wn4 = warp & 3;

    float acc[4][4][4];
    #pragma unroll
    for (int a = 0; a < 4; a++)
        #pragma unroll
        for (int b = 0; b < 4; b++)
            #pragma unroll
            for (int q = 0; q < 4; q++) acc[a][b][q] = 0.0f;

    const int nst = Kdim / BK;
    load_stage(sb,         Af, Bf, tile_m, tile_n, Mdim, Kdim, 0, tid);
    load_stage(sb + STAGE, Af, Bf, tile_m, tile_n, Mdim, Kdim, 1, tid);

    const uint32_t a_off = (uint32_t)(wm2*64 + (lane & 7) + ((lane >> 3) & 1) * 8) * PADB
                         + ((lane >> 4) * 16);
    const uint32_t b_off = (uint32_t)(wn4*32 + (lane & 7) + ((lane >> 4) & 1) * 8) * PADB
                         + (((lane >> 3) & 1) * 16);

    for (int s = 0; s < nst; s++) {
        if (s + 1 < nst) asm volatile("cp.async.wait_group 1;" ::: "memory");
        else             asm volatile("cp.async.wait_group 0;" ::: "memory");
        __syncthreads();
        if (s + 2 < nst)
            load_stage(sb + ((s + 2) % NSTAGE) * STAGE, Af, Bf,
                       tile_m, tile_n, Mdim, Kdim, s + 2, tid);
        const uint32_t st = sb + (s % NSTAGE) * STAGE;

        #pragma unroll
        for (int ks = 0; ks < 4; ks++) {
            uint32_t ah[4][4], bh[4][2];
            #pragma unroll
            for (int mi = 0; mi < 4; mi++)
                ldsm4(ah[mi], st + a_off + mi * (16 * PADB) + ks * 32);
            #pragma unroll
            for (int p = 0; p < 2; p++) {
                uint32_t r[4];
                ldsm4(r, st + A_ARR + b_off + p * (16 * PADB) + ks * 32);
                bh[2*p][0] = r[0]; bh[2*p][1] = r[1];
                bh[2*p+1][0] = r[2]; bh[2*p+1][1] = r[3];
            }
            #pragma unroll
            for (int mi = 0; mi < 4; mi++)
                #pragma unroll
                for (int ni = 0; ni < 4; ni++)
                    mma16816(acc[mi][ni], ah[mi], bh[ni]);
        }
    }

    // ---- epilogue (fp16 out) ----
    const int er = lane >> 2;
    const int ec = (lane & 3) * 2;
    #pragma unroll
    for (int mi = 0; mi < 4; mi++) {
        const int gm0 = tile_m + wm2*64 + mi*16 + er;
        #pragma unroll
        for (int ni = 0; ni < 4; ni++) {
            const int gn = tile_n + wn4*32 + ni*8 + ec;
            float bx = 0.f, by = 0.f;
            if (bias) { float2 bb = *reinterpret_cast<const float2*>(bias + gn);
                        bx = bb.x; by = bb.y; }
            float v0 = acc[mi][ni][0] + bx, v1 = acc[mi][ni][1] + by;
            float v2 = acc[mi][ni][2] + bx, v3 = acc[mi][ni][3] + by;
            if (act == 1) {
                v0 = fmaxf(v0, 0.f); v1 = fmaxf(v1, 0.f);
                v2 = fmaxf(v2, 0.f); v3 = fmaxf(v3, 0.f);
            } else if (act == 2) {
                v0 = tanhf(v0); v1 = tanhf(v1); v2 = tanhf(v2); v3 = tanhf(v3);
            }
            if (gm0 < Mdim) {
                __half2 h; h.x = __float2half_rn(v0); h.y = __float2half_rn(v1);
                *reinterpret_cast<__half2*>(Chalf + (size_t)gm0 * Ndim + gn) = h;
            }
            if (gm0 + 8 < Mdim) {
                __half2 h; h.x = __float2half_rn(v2); h.y = __float2half_rn(v3);
                *reinterpret_cast<__half2*>(Chalf + (size_t)(gm0+8) * Ndim + gn) = h;
            }
        }
    }
}

// ---------------- fp32 -> fp16 convert helpers ----------------
__device__ __forceinline__ void cvt_one(const float* in, __half* o, int i) {
    float4 v = *reinterpret_cast<const float4*>(in + (size_t)i * 4);
    __half2 h0, h1;
    h0.x = __float2half_rn(v.x); h0.y = __float2half_rn(v.y);
    h1.x = __float2half_rn(v.z); h1.y = __float2half_rn(v.w);
    uint2 u;
    u.x = *reinterpret_cast<uint32_t*>(&h0);
    u.y = *reinterpret_cast<uint32_t*>(&h1);
    *reinterpret_cast<uint2*>(o + (size_t)i * 4) = u;
}
__global__ void cvt4_kernel(const float* i1, __half* o1, int n1,
                            const float* i2, __half* o2, int n2,
                            const float* i3, __half* o3, int n3,
                            const float* i4, __half* o4, int n4) {
    int i = blockIdx.x * blockDim.x + threadIdx.x;
    if (i < n1) { cvt_one(i1, o1, i); return; }
    i -= n1;
    if (i < n2) { cvt_one(i2, o2, i); return; }
    i -= n2;
    if (i < n3) { cvt_one(i3, o3, i); return; }
    i -= n3;
    if (i < n4) cvt_one(i4, o4, i);
}

// ---------------- fused span-id + PE table + wqkv convert ----------------
#define PE_BLKS   (M_*E_/512)            // 512
#define CVTQ_N    (2*3*E_*E_/4)          // 393216 float4s
#define CVTQ_BLKS ((CVTQ_N + 511)/512)   // 768
__global__ void spanpe_kernel(const int* __restrict__ pos1, int* __restrict__ span,
                              float* __restrict__ pe,
                              const float* __restrict__ wqkv, __half* __restrict__ WQf) {
    if (blockIdx.x < 32) {
        int b = blockIdx.x;
        int j = threadIdx.x;
        __shared__ int firstZero;
        span[b*M_ + j] = -1;
        if (j == 0) firstZero = M_;
        __syncthreads();
        int endv = pos1[((size_t)b*M_ + j)*2 + 1];
        if (endv == 0) atomicMin(&firstZero, j);
        __syncthreads();
        if (j < firstZero) {
            int st = pos1[((size_t)b*M_ + j)*2];
            int en = endv; if (en > M_) en = M_;
            for (int k = st; k < en; k++)
                atomicMax(&span[b*M_ + k], j);
        }
    } else if (blockIdx.x < 32 + PE_BLKS) {
        int idx = (blockIdx.x - 32) * 512 + threadIdx.x;
        int pos = idx / E_, i = idx % E_;
        double e2  = (double)((i / 2) * 2);
        double ang = (double)pos / pow(10000.0, e2 / (double)E_);
        pe[idx] = (float)((i % 2 == 0) ? sin(ang) : cos(ang));
    } else {
        int i = (blockIdx.x - 32 - PE_BLKS) * 512 + threadIdx.x;
        if (i < CVTQ_N) cvt_one(wqkv, WQf, i);
    }
}

// ---------------- build x: warp per row, vectorized ----------------
__global__ void build_x_kernel(const int* __restrict__ pos2,
                               const float* __restrict__ fbase,
                               const float* __restrict__ emb,
                               const int* __restrict__ span,
                               const float* __restrict__ pe,
                               __half* __restrict__ Xf) {
    int row  = blockIdx.x * 8 + (threadIdx.x >> 5);
    int lane = threadIdx.x & 31;
    int b = row / S_, s = row % S_;

    const float* srcA = nullptr;
    const float* srcB = nullptr;
    if (s == 0) {
        srcA = emb + (size_t)1 * E_;
    } else {
        int k = s - 1;
        int sid = span[b*M_ + k];
        if (sid >= 0) {
            int p = pos2[b*M_ + sid];
            srcA = (p == 0) ? nullptr : emb + (size_t)p * E_;
            srcB = pe + (size_t)sid * E_;
        } else {
            srcA = fbase + ((size_t)b*M_ + k) * E_;
        }
    }

    __half* dst = Xf + (size_t)row * E_;
    #pragma unroll
    for (int j = 0; j < 4; j++) {
        int i4 = lane + 32*j;
        float4 v = srcA ? reinterpret_cast<const float4*>(srcA)[i4]
                        : make_float4(0.f, 0.f, 0.f, 0.f);
        if (srcB) {
            float4 p4 = reinterpret_cast<const float4*>(srcB)[i4];
            v.x += p4.x; v.y += p4.y; v.z += p4.z; v.w += p4.w;
        }
        __half2 h0, h1;
        h0.x = __float2half_rn(v.x); h0.y = __float2half_rn(v.y);
        h1.x = __float2half_rn(v.z); h1.y = __float2half_rn(v.w);
        uint2 u;
        u.x = *reinterpret_cast<uint32_t*>(&h0);
        u.y = *reinterpret_cast<uint32_t*>(&h1);
        *reinterpret_cast<uint2*>(dst + 4*i4) = u;
    }
}

// ---------------- fused attention over the B axis (vectorized loads) ----------------
__global__ void attn_kernel(const __half* __restrict__ QKV,
                            __half* __restrict__ CXf) {
    int z = blockIdx.x;
    int s = z / NHEAD_, h = z % NHEAD_;
    __shared__ float q[B_][DH_];
    __shared__ float k[B_][DH_ + 1];   // pad: conflict-free scores
    __shared__ float v[B_][DH_];
    __shared__ float sc[B_][B_ + 1];

    const __half* base = QKV + (size_t)s * 3*E_ + (size_t)h * DH_;
    int t = threadIdx.x;

    // 768 uint4 loads (3 matrices x 32 rows x 8 chunks of 8 halves)
    #pragma unroll
    for (int iter = 0; iter < 3; iter++) {
        int i = t + 256*iter;
        int mat = i >> 8, rem = i & 255;
        int row = rem >> 3, c = rem & 7;
        const __half* src = base + (size_t)row * S_ * 3*E_ + mat * E_ + c*8;
        uint4 u = *reinterpret_cast<const uint4*>(src);
        const __half2* hp = reinterpret_cast<const __half2*>(&u);
        float2 f0 = __half22float2(hp[0]), f1 = __half22float2(hp[1]);
        float2 f2 = __half22float2(hp[2]), f3 = __half22float2(hp[3]);
        if (mat == 0) {
            *reinterpret_cast<float4*>(&q[row][c*8])     = make_float4(f0.x, f0.y, f1.x, f1.y);
            *reinterpret_cast<float4*>(&q[row][c*8 + 4]) = make_float4(f2.x, f2.y, f3.x, f3.y);
        } else if (mat == 1) {
            float* kr = &k[row][c*8];
            kr[0]=f0.x; kr[1]=f0.y; kr[2]=f1.x; kr[3]=f1.y;
            kr[4]=f2.x; kr[5]=f2.y; kr[6]=f3.x; kr[7]=f3.y;
        } else {
            *reinterpret_cast<float4*>(&v[row][c*8])     = make_float4(f0.x, f0.y, f1.x, f1.y);
            *reinterpret_cast<float4*>(&v[row][c*8 + 4]) = make_float4(f2.x, f2.y, f3.x, f3.y);
        }
    }
    __syncthreads();

    for (int i = t; i < B_*B_; i += 256) {
        int l = i / B_, m = i % B_;
        float acc = 0.0f;
        #pragma unroll
        for (int d = 0; d < DH_; d++) acc += q[l][d] * k[m][d];
        sc[l][m] = acc * 0.125f;
    }
    __syncthreads();

    int warp = t >> 5, lane = t & 31;
    for (int l = warp; l < B_; l += 8) {
        float val = sc[l][lane];
        float mx = val;
        #pragma unroll
        for (int o = 16; o; o >>= 1) mx = fmaxf(mx, __shfl_xor_sync(0xffffffffu, mx, o));
        float e = expf(val - mx);
        float sum = e;
        #pragma unroll
        for (int o = 16; o; o >>= 1) sum += __shfl_xor_sync(0xffffffffu, sum, o);
        sc[l][lane] = e / sum;
    }
    __syncthreads();

    for (int i = t; i < B_*DH_; i += 256) {
        int l = i / DH_, d = i % DH_;
        float acc = 0.0f;
        #pragma unroll
        for (int m = 0; m < B_; m++) acc += sc[l][m] * v[m][d];
        CXf[((size_t)l * S_ + s) * E_ + (size_t)h * DH_ + d] = __float2half_rn(acc);
    }
}

// ---------------- residual add + layernorm: all-fp16 IO, warp per row ------
__global__ void add_ln_kernel(__half* __restrict__ Xf, const __half* __restrict__ Yh,
                              const float* __restrict__ w, const float* __restrict__ b) {
    int row  = blockIdx.x * 8 + (threadIdx.x >> 5);
    int lane = threadIdx.x & 31;
    const uint4* xr = reinterpret_cast<const uint4*>(Xf + (size_t)row * E_);
    const uint4* yr = reinterpret_cast<const uint4*>(Yh + (size_t)row * E_);

    float vals[16];
    float s = 0.f, s2 = 0.f;
    #pragma unroll
    for (int j = 0; j < 2; j++) {
        uint4 xa = xr[lane + 32*j];
        uint4 ya = yr[lane + 32*j];
        const __half2* xh = reinterpret_cast<const __half2*>(&xa);
        const __half2* yh = reinterpret_cast<const __half2*>(&ya);
        #pragma unroll
        for (int q = 0; q < 4; q++) {
            float2 fx = __half22float2(xh[q]);
            float2 fy = __half22float2(yh[q]);
            float a0 = fx.x + fy.x, a1 = fx.y + fy.y;
            vals[j*8 + 2*q]     = a0;
            vals[j*8 + 2*q + 1] = a1;
            s  += a0 + a1;
            s2 += a0*a0 + a1*a1;
        }
    }
    #pragma unroll
    for (int o = 16; o; o >>= 1) {
        s  += __shfl_xor_sync(0xffffffffu, s,  o);
        s2 += __shfl_xor_sync(0xffffffffu, s2, o);
    }
    float mean = s * (1.0f / E_);
    float rstd = rsqrtf(s2 * (1.0f / E_) - mean*mean + 1e-5f);

    uint4* xw = reinterpret_cast<uint4*>(Xf + (size_t)row * E_);
    #pragma unroll
    for (int j = 0; j < 2; j++) {
        int base = (lane + 32*j) * 8;
        uint4 o;
        __half2* oh = reinterpret_cast<__half2*>(&o);
        #pragma unroll
        for (int q = 0; q < 4; q++) {
            float2 wv = *reinterpret_cast<const float2*>(w + base + 2*q);
            float2 bv = *reinterpret_cast<const float2*>(b + base + 2*q);
            float o0 = (vals[j*8 + 2*q]     - mean) * rstd * wv.x + bv.x;
            float o1 = (vals[j*8 + 2*q + 1] - mean) * rstd * wv.y + bv.y;
            __half2 h; h.x = __float2half_rn(o0); h.y = __float2half_rn(o1);
            oh[q] = h;
        }
        xw[lane + 32*j] = o;
    }
}

// ---------------- discriminator head (vectorized) ----------------
__global__ void disc_kernel(const float* __restrict__ bert,
                            const __half* __restrict__ posf,
                            const float* __restrict__ wd,
                            const float* __restrict__ bd,
                            float* __restrict__ out, int ntok) {
    int n = (blockIdx.x * blockDim.x + threadIdx.x) >> 5;
    int lane = threadIdx.x & 31;
    if (n >= ntok) return;
    float acc = 0.0f;
    const float4* br4 = reinterpret_cast<const float4*>(bert + (size_t)n * F_);
    const float4* wd4 = reinterpret_cast<const float4*>(wd);
    #pragma unroll
    for (int j = 0; j < 6; j++) {
        int idx = lane + 32*j;
        float4 v = br4[idx];
        float4 wv = wd4[idx];
        acc += v.x*wv.x + v.y*wv.y + v.z*wv.z + v.w*wv.w;
    }
    const uint4* pr4 = reinterpret_cast<const uint4*>(posf + (size_t)n * F_);
    #pragma unroll
    for (int j = 0; j < 3; j++) {
        int idx = lane + 32*j;
        uint4 u = pr4[idx];
        const __half2* ph = reinterpret_cast<const __half2*>(&u);
        const float* wp = wd + F_ + idx*8;
        #pragma unroll
        for (int q = 0; q < 4; q++) {
            float2 f = __half22float2(ph[q]);
            acc += f.x * wp[2*q] + f.y * wp[2*q + 1];
        }
    }
    #pragma unroll
    for (int o = 16; o; o >>= 1) acc += __shfl_xor_sync(0xffffffffu, acc, o);
    if (lane == 0) out[n] = 1.0f / (1.0f + expf(-(acc + bd[0])));
}

// ---------------- host orchestration ----------------
static inline int cdiv(int a, int b) { return (a + b - 1) / b; }

extern "C" void kernel_launch(void* const* d_in, const int* in_sizes, int n_in,
                              void* d_out, int out_size) {
    const int*   pos1  = (const int*)d_in[0];
    const int*   pos2  = (const int*)d_in[1];
    const float* bert  = (const float*)d_in[2];
    const float* fbase = (const float*)d_in[3];
    const float* emb   = (const float*)d_in[4];
    const float* wqkv  = (const float*)d_in[5];
    const float* bqkv  = (const float*)d_in[6];
    const float* wo    = (const float*)d_in[7];
    const float* bo    = (const float*)d_in[8];
    const float* ln1w  = (const float*)d_in[9];
    const float* ln1b  = (const float*)d_in[10];
    const float* ln2w  = (const float*)d_in[11];
    const float* ln2b  = (const float*)d_in[12];
    const float* w1    = (const float*)d_in[13];
    const float* b1    = (const float*)d_in[14];
    const float* w2    = (const float*)d_in[15];
    const float* b2    = (const float*)d_in[16];
    const float* wm    = (const float*)d_in[17];
    const float* wd    = (const float*)d_in[18];
    const float* bd    = (const float*)d_in[19];
    float* out = (float*)d_out;

    float *PE; int* SPAN;
    __half *Xf, *Yh, *QKVf, *CXf, *Hf, *POSFh, *WQf, *WOf, *W1f, *W2f, *WMf;
    cudaGetSymbolAddress((void**)&PE,    d_PE);
    cudaGetSymbolAddress((void**)&SPAN,  d_SPAN);
    cudaGetSymbolAddress((void**)&Xf,    d_Xf);
    cudaGetSymbolAddress((void**)&Yh,    d_Yh);
    cudaGetSymbolAddress((void**)&QKVf,  d_QKVf);
    cudaGetSymbolAddress((void**)&CXf,   d_CXf);
    cudaGetSymbolAddress((void**)&Hf,    d_Hf);
    cudaGetSymbolAddress((void**)&POSFh, d_POSFh);
    cudaGetSymbolAddress((void**)&WQf,   d_WQf);
    cudaGetSymbolAddress((void**)&WOf,   d_WOf);
    cudaGetSymbolAddress((void**)&W1f,   d_W1f);
    cudaGetSymbolAddress((void**)&W2f,   d_W2f);
    cudaGetSymbolAddress((void**)&WMf,   d_WMf);

    cudaFuncSetAttribute(gemm_tc, cudaFuncAttributeMaxDynamicSharedMemorySize, SMEM_GEMM);

    // launch 0: span + PE + convert wqkv (fused)
    spanpe_kernel<<<32 + PE_BLKS + CVTQ_BLKS, 512>>>(pos1, SPAN, PE, wqkv, WQf);
    // launch 1: build x
    build_x_kernel<<<NTOK/8, 256>>>(pos2, fbase, emb, SPAN, PE, Xf);

    const int MY = cdiv(NTOK, BM);   // 129
    bool cvt_rest_done = false;

    for (int l = 0; l < 2; l++) {
        const size_t oq = (size_t)l * 3*E_ * E_;
        const size_t oo = (size_t)l * E_ * E_;
        const size_t o1 = (size_t)l * DFF_ * E_;
        const size_t o2 = (size_t)l * E_ * DFF_;

        { dim3 g(3*E_/BN, MY);   // QKV -> fp16 (launch 2, layer 0)
          gemm_tc<<<g, NTHR_G, SMEM_GEMM>>>(Xf, WQf+oq,
              QKVf, NTOK, 3*E_, E_, bqkv + l*3*E_, 0); }

        attn_kernel<<<S_*NHEAD_, 256>>>(QKVf, CXf);   // launch 3 on layer 0 -> ncu

        if (!cvt_rest_done) {    // launch 4: convert wo,w1,w2,wm
            int n2 = 2*E_*E_/4, n3 = 2*DFF_*E_/4, n4 = 2*E_*DFF_/4, n5 = F_*E_/4;
            cvt4_kernel<<<cdiv(n2+n3+n4+n5, 256), 256>>>(
                wo, WOf, n2, w1, W1f, n3, w2, W2f, n4, wm, WMf, n5);
            cvt_rest_done = true;
        }

        { dim3 g(E_/BN, MY);     // Wo -> fp16 Y
          gemm_tc<<<g, NTHR_G, SMEM_GEMM>>>(CXf, WOf+oo,
              Yh, NTOK, E_, E_, bo + l*E_, 0); }

        add_ln_kernel<<<NTOK/8, 256>>>(Xf, Yh, ln1w + l*E_, ln1b + l*E_);

        { dim3 g(DFF_/BN, MY);   // FFN1 -> f16 H
          gemm_tc<<<g, NTHR_G, SMEM_GEMM>>>(Xf, W1f+o1,
              Hf, NTOK, DFF_, E_, b1 + l*DFF_, 1); }

        { dim3 g(E_/BN, MY);     // FFN2 -> fp16 Y
          gemm_tc<<<g, NTHR_G, SMEM_GEMM>>>(Hf, W2f+o2,
              Yh, NTOK, E_, DFF_, b2 + l*E_, 0); }

        add_ln_kernel<<<NTOK/8, 256>>>(Xf, Yh, ln2w + l*E_, ln2b + l*E_);
    }

    { dim3 g(F_/BN, MY);         // pos_feature = tanh(X @ wm^T), fp16 out
      gemm_tc<<<g, NTHR_G, SMEM_GEMM>>>(Xf, WMf,
          POSFh, NTOK, F_, E_, nullptr, 2); }

    disc_kernel<<<cdiv(NTOK*32, 256), 256>>>(bert, POSFh, wd, bd, out, NTOK);
}

// round 17
// speedup vs baseline: 1.1091x; 1.0362x over previous
#include <cuda_runtime.h>
#include <cuda_fp16.h>
#include <math.h>
#include <stdint.h>

// ---------------- problem constants ----------------
#define B_    32
#define M_    512
#define E_    512
#define S_    513
#define NTOK  (B_*S_)          // 16416
#define NHEAD_ 8
#define DH_   64
#define DFF_  2048
#define F_    768

// ---------------- scratch ----------------
__device__ float d_PE[M_*E_];
__device__ int   d_SPAN[B_*M_];

// ---------------- fp16 activation / weight buffers ----------------
__device__ __align__(16) __half d_Xf   [(size_t)NTOK*E_];
__device__ __align__(16) __half d_Yh   [(size_t)NTOK*E_];
__device__ __align__(16) __half d_QKVf [(size_t)NTOK*3*E_];
__device__ __align__(16) __half d_CXf  [(size_t)NTOK*E_];
__device__ __align__(16) __half d_Hf   [(size_t)NTOK*DFF_];
__device__ __align__(16) __half d_POSFh[(size_t)NTOK*F_];
__device__ __align__(16) __half d_WQf  [(size_t)2*3*E_*E_];
__device__ __align__(16) __half d_WOf  [(size_t)2*E_*E_];
__device__ __align__(16) __half d_W1f  [(size_t)2*DFF_*E_];
__device__ __align__(16) __half d_W2f  [(size_t)2*E_*DFF_];
__device__ __align__(16) __half d_WMf  [(size_t)F_*E_];

// ================= fp16 tensor-core GEMM (BK=64, 2 CTAs/SM) ========
#define BM 128
#define BN 128
#define BK 64
#define PADB 144
#define A_ARR (128*PADB)
#define B_ARR (128*PADB)
#define STAGE (A_ARR + B_ARR)
#define NSTAGE 3
#define SMEM_GEMM (NSTAGE*STAGE)
#define NTHR_G 256

__device__ __forceinline__ uint32_t smem_u32(const void* p) {
    uint32_t a;
    asm("{ .reg .u64 t; cvta.to.shared.u64 t, %1; cvt.u32.u64 %0, t; }"
        : "=r"(a) : "l"(p));
    return a;
}
__device__ __forceinline__ void ldsm4(uint32_t* r, uint32_t addr) {
    asm volatile("ldmatrix.sync.aligned.m8n8.x4.shared.b16 {%0,%1,%2,%3}, [%4];"
        : "=r"(r[0]), "=r"(r[1]), "=r"(r[2]), "=r"(r[3]) : "r"(addr));
}
__device__ __forceinline__ void mma16816(float* c, const uint32_t* a, const uint32_t* b) {
    asm volatile(
        "mma.sync.aligned.m16n8k16.row.col.f32.f16.f16.f32 "
        "{%0,%1,%2,%3}, {%4,%5,%6,%7}, {%8,%9}, {%0,%1,%2,%3};"
        : "+f"(c[0]), "+f"(c[1]), "+f"(c[2]), "+f"(c[3])
        : "r"(a[0]), "r"(a[1]), "r"(a[2]), "r"(a[3]), "r"(b[0]), "r"(b[1]));
}
__device__ __forceinline__ void cpa16(uint32_t dst, const void* src, int srcsize) {
    asm volatile("cp.async.cg.shared.global [%0], [%1], 16, %2;"
                 :: "r"(dst), "l"(src), "r"(srcsize));
}

__device__ __forceinline__ void load_stage(
    uint32_t st,
    const __half* __restrict__ Af, const __half* __restrict__ Bf,
    int tile_m, int tile_n, int Mdim, int Kdim, int kc, int tid)
{
    const int k0 = kc * BK;
    #pragma unroll
    for (int i = 0; i < 4; i++) {
        int id = tid + NTHR_G*i;
        int row = id >> 3, c = id & 7;
        const __half* src = Af + (size_t)(tile_m + row) * Kdim + k0 + c*8;
        cpa16(st + row*PADB + c*16, src, (tile_m + row) < Mdim ? 16 : 0);
    }
    #pragma unroll
    for (int i = 0; i < 4; i++) {
        int id = tid + NTHR_G*i;
        int row = id >> 3, c = id & 7;
        const __half* src = Bf + (size_t)(tile_n + row) * Kdim + k0 + c*8;
        cpa16(st + A_ARR + row*PADB + c*16, src, 16);
    }
    asm volatile("cp.async.commit_group;" ::: "memory");
}

__global__ __launch_bounds__(NTHR_G, 2)
void gemm_tc(const __half* __restrict__ Af, const __half* __restrict__ Bf,
             __half* __restrict__ Chalf,
             int Mdim, int Ndim, int Kdim,
             const float* __restrict__ bias, int act)
{
    extern __shared__ __align__(16) char smem[];
    const uint32_t sb = smem_u32(smem);
    const int tid    = threadIdx.x;
    const int tile_m = blockIdx.y * BM;
    const int tile_n = blockIdx.x * BN;
    const int warp = tid >> 5, lane = tid & 31;
    const int wm2 = warp >> 2, wn4 = warp & 3;

    float acc[4][4][4];
    #pragma unroll
    for (int a = 0; a < 4; a++)
        #pragma unroll
        for (int b = 0; b < 4; b++)
            #pragma unroll
            for (int q = 0; q < 4; q++) acc[a][b][q] = 0.0f;

    const int nst = Kdim / BK;
    load_stage(sb,         Af, Bf, tile_m, tile_n, Mdim, Kdim, 0, tid);
    load_stage(sb + STAGE, Af, Bf, tile_m, tile_n, Mdim, Kdim, 1, tid);

    const uint32_t a_off = (uint32_t)(wm2*64 + (lane & 7) + ((lane >> 3) & 1) * 8) * PADB
                         + ((lane >> 4) * 16);
    const uint32_t b_off = (uint32_t)(wn4*32 + (lane & 7) + ((lane >> 4) & 1) * 8) * PADB
                         + (((lane >> 3) & 1) * 16);

    for (int s = 0; s < nst; s++) {
        if (s + 1 < nst) asm volatile("cp.async.wait_group 1;" ::: "memory");
        else             asm volatile("cp.async.wait_group 0;" ::: "memory");
        __syncthreads();
        if (s + 2 < nst)
            load_stage(sb + ((s + 2) % NSTAGE) * STAGE, Af, Bf,
                       tile_m, tile_n, Mdim, Kdim, s + 2, tid);
        const uint32_t st = sb + (s % NSTAGE) * STAGE;

        #pragma unroll
        for (int ks = 0; ks < 4; ks++) {
            uint32_t ah[4][4], bh[4][2];
            #pragma unroll
            for (int mi = 0; mi < 4; mi++)
                ldsm4(ah[mi], st + a_off + mi * (16 * PADB) + ks * 32);
            #pragma unroll
            for (int p = 0; p < 2; p++) {
                uint32_t r[4];
                ldsm4(r, st + A_ARR + b_off + p * (16 * PADB) + ks * 32);
                bh[2*p][0] = r[0]; bh[2*p][1] = r[1];
                bh[2*p+1][0] = r[2]; bh[2*p+1][1] = r[3];
            }
            #pragma unroll
            for (int mi = 0; mi < 4; mi++)
                #pragma unroll
                for (int ni = 0; ni < 4; ni++)
                    mma16816(acc[mi][ni], ah[mi], bh[ni]);
        }
    }

    // ---- epilogue (fp16 out) ----
    const int er = lane >> 2;
    const int ec = (lane & 3) * 2;
    #pragma unroll
    for (int mi = 0; mi < 4; mi++) {
        const int gm0 = tile_m + wm2*64 + mi*16 + er;
        #pragma unroll
        for (int ni = 0; ni < 4; ni++) {
            const int gn = tile_n + wn4*32 + ni*8 + ec;
            float bx = 0.f, by = 0.f;
            if (bias) { float2 bb = *reinterpret_cast<const float2*>(bias + gn);
                        bx = bb.x; by = bb.y; }
            float v0 = acc[mi][ni][0] + bx, v1 = acc[mi][ni][1] + by;
            float v2 = acc[mi][ni][2] + bx, v3 = acc[mi][ni][3] + by;
            if (act == 1) {
                v0 = fmaxf(v0, 0.f); v1 = fmaxf(v1, 0.f);
                v2 = fmaxf(v2, 0.f); v3 = fmaxf(v3, 0.f);
            } else if (act == 2) {
                v0 = tanhf(v0); v1 = tanhf(v1); v2 = tanhf(v2); v3 = tanhf(v3);
            }
            if (gm0 < Mdim) {
                __half2 h; h.x = __float2half_rn(v0); h.y = __float2half_rn(v1);
                *reinterpret_cast<__half2*>(Chalf + (size_t)gm0 * Ndim + gn) = h;
            }
            if (gm0 + 8 < Mdim) {
                __half2 h; h.x = __float2half_rn(v2); h.y = __float2half_rn(v3);
                *reinterpret_cast<__half2*>(Chalf + (size_t)(gm0+8) * Ndim + gn) = h;
            }
        }
    }
}

// ---------------- fp32 -> fp16 convert helpers ----------------
__device__ __forceinline__ void cvt_one(const float* in, __half* o, int i) {
    float4 v = *reinterpret_cast<const float4*>(in + (size_t)i * 4);
    __half2 h0, h1;
    h0.x = __float2half_rn(v.x); h0.y = __float2half_rn(v.y);
    h1.x = __float2half_rn(v.z); h1.y = __float2half_rn(v.w);
    uint2 u;
    u.x = *reinterpret_cast<uint32_t*>(&h0);
    u.y = *reinterpret_cast<uint32_t*>(&h1);
    *reinterpret_cast<uint2*>(o + (size_t)i * 4) = u;
}
__global__ void cvt4_kernel(const float* i1, __half* o1, int n1,
                            const float* i2, __half* o2, int n2,
                            const float* i3, __half* o3, int n3,
                            const float* i4, __half* o4, int n4) {
    int i = blockIdx.x * blockDim.x + threadIdx.x;
    if (i < n1) { cvt_one(i1, o1, i); return; }
    i -= n1;
    if (i < n2) { cvt_one(i2, o2, i); return; }
    i -= n2;
    if (i < n3) { cvt_one(i3, o3, i); return; }
    i -= n3;
    if (i < n4) cvt_one(i4, o4, i);
}

// ---------------- fused span-id + PE table + wqkv convert ----------------
#define PE_BLKS   (M_*E_/512)            // 512
#define CVTQ_N    (2*3*E_*E_/4)          // 393216 float4s
#define CVTQ_BLKS ((CVTQ_N + 511)/512)   // 768
__global__ void spanpe_kernel(const int* __restrict__ pos1, int* __restrict__ span,
                              float* __restrict__ pe,
                              const float* __restrict__ wqkv, __half* __restrict__ WQf) {
    if (blockIdx.x < 32) {
        int b = blockIdx.x;
        int j = threadIdx.x;
        __shared__ int firstZero;
        span[b*M_ + j] = -1;
        if (j == 0) firstZero = M_;
        __syncthreads();
        int endv = pos1[((size_t)b*M_ + j)*2 + 1];
        if (endv == 0) atomicMin(&firstZero, j);
        __syncthreads();
        if (j < firstZero) {
            int st = pos1[((size_t)b*M_ + j)*2];
            int en = endv; if (en > M_) en = M_;
            for (int k = st; k < en; k++)
                atomicMax(&span[b*M_ + k], j);
        }
    } else if (blockIdx.x < 32 + PE_BLKS) {
        int idx = (blockIdx.x - 32) * 512 + threadIdx.x;
        int pos = idx / E_, i = idx % E_;
        double e2  = (double)((i / 2) * 2);
        double ang = (double)pos / pow(10000.0, e2 / (double)E_);
        pe[idx] = (float)((i % 2 == 0) ? sin(ang) : cos(ang));
    } else {
        int i = (blockIdx.x - 32 - PE_BLKS) * 512 + threadIdx.x;
        if (i < CVTQ_N) cvt_one(wqkv, WQf, i);
    }
}

// ---------------- build x: warp per row, vectorized ----------------
__global__ void build_x_kernel(const int* __restrict__ pos2,
                               const float* __restrict__ fbase,
                               const float* __restrict__ emb,
                               const int* __restrict__ span,
                               const float* __restrict__ pe,
                               __half* __restrict__ Xf) {
    int row  = blockIdx.x * 8 + (threadIdx.x >> 5);
    int lane = threadIdx.x & 31;
    int b = row / S_, s = row % S_;

    const float* srcA = nullptr;
    const float* srcB = nullptr;
    if (s == 0) {
        srcA = emb + (size_t)1 * E_;
    } else {
        int k = s - 1;
        int sid = span[b*M_ + k];
        if (sid >= 0) {
            int p = pos2[b*M_ + sid];
            srcA = (p == 0) ? nullptr : emb + (size_t)p * E_;
            srcB = pe + (size_t)sid * E_;
        } else {
            srcA = fbase + ((size_t)b*M_ + k) * E_;
        }
    }

    __half* dst = Xf + (size_t)row * E_;
    #pragma unroll
    for (int j = 0; j < 4; j++) {
        int i4 = lane + 32*j;
        float4 v = srcA ? reinterpret_cast<const float4*>(srcA)[i4]
                        : make_float4(0.f, 0.f, 0.f, 0.f);
        if (srcB) {
            float4 p4 = reinterpret_cast<const float4*>(srcB)[i4];
            v.x += p4.x; v.y += p4.y; v.z += p4.z; v.w += p4.w;
        }
        __half2 h0, h1;
        h0.x = __float2half_rn(v.x); h0.y = __float2half_rn(v.y);
        h1.x = __float2half_rn(v.z); h1.y = __float2half_rn(v.w);
        uint2 u;
        u.x = *reinterpret_cast<uint32_t*>(&h0);
        u.y = *reinterpret_cast<uint32_t*>(&h1);
        *reinterpret_cast<uint2*>(dst + 4*i4) = u;
    }
}

// ---------------- fused attention: half2-resident smem (halved LDS traffic) ----
__global__ void attn_kernel(const __half* __restrict__ QKV,
                            __half* __restrict__ CXf) {
    int z = blockIdx.x;
    int s = z / NHEAD_, h = z % NHEAD_;
    // half2-packed rows; stride 33 words -> bank (row*33 + d) % 32 = (row + d) % 32,
    // conflict-free for lane=row (k by m) and lane=d (v by d2) patterns.
    __shared__ uint32_t q2[B_][33];
    __shared__ uint32_t k2[B_][33];
    __shared__ uint32_t v2[B_][33];
    __shared__ float    sc[B_][B_ + 1];

    const __half* base = QKV + (size_t)s * 3*E_ + (size_t)h * DH_;
    int t = threadIdx.x;

    // 768 uint4 loads -> 4 packed half2 words each (no conversion at load)
    #pragma unroll
    for (int iter = 0; iter < 3; iter++) {
        int i = t + 256*iter;
        int mat = i >> 8, rem = i & 255;
        int row = rem >> 3, c = rem & 7;
        const __half* src = base + (size_t)row * S_ * 3*E_ + mat * E_ + c*8;
        uint4 u = *reinterpret_cast<const uint4*>(src);
        uint32_t* dr = (mat == 0) ? q2[row] : (mat == 1) ? k2[row] : v2[row];
        dr[c*4 + 0] = u.x; dr[c*4 + 1] = u.y; dr[c*4 + 2] = u.z; dr[c*4 + 3] = u.w;
    }
    __syncthreads();

    // scores: q broadcast, k conflict-free; 64 LDS per (l,m) instead of 128
    for (int i = t; i < B_*B_; i += 256) {
        int l = i >> 5, m = i & 31;
        float acc = 0.0f;
        #pragma unroll
        for (int d2 = 0; d2 < DH_/2; d2++) {
            float2 fq = __half22float2(*reinterpret_cast<const __half2*>(&q2[l][d2]));
            float2 fk = __half22float2(*reinterpret_cast<const __half2*>(&k2[m][d2]));
            acc += fq.x * fk.x + fq.y * fk.y;
        }
        sc[l][m] = acc * 0.125f;
    }
    __syncthreads();

    int warp = t >> 5, lane = t & 31;
    for (int l = warp; l < B_; l += 8) {
        float val = sc[l][lane];
        float mx = val;
        #pragma unroll
        for (int o = 16; o; o >>= 1) mx = fmaxf(mx, __shfl_xor_sync(0xffffffffu, mx, o));
        float e = expf(val - mx);
        float sum = e;
        #pragma unroll
        for (int o = 16; o; o >>= 1) sum += __shfl_xor_sync(0xffffffffu, sum, o);
        sc[l][lane] = e / sum;
    }
    __syncthreads();

    // ctx: each thread computes one half2 output pair; sc broadcast, v conflict-free
    for (int i = t; i < B_*(DH_/2); i += 256) {
        int l = i >> 5, d2 = i & 31;
        float a0 = 0.0f, a1 = 0.0f;
        #pragma unroll
        for (int m = 0; m < B_; m++) {
            float p = sc[l][m];
            float2 fv = __half22float2(*reinterpret_cast<const __half2*>(&v2[m][d2]));
            a0 += p * fv.x;
            a1 += p * fv.y;
        }
        __half2 hh; hh.x = __float2half_rn(a0); hh.y = __float2half_rn(a1);
        *reinterpret_cast<__half2*>(
            CXf + ((size_t)l * S_ + s) * E_ + (size_t)h * DH_ + 2*d2) = hh;
    }
}

// ---------------- residual add + layernorm: all-fp16 IO, warp per row ------
__global__ void add_ln_kernel(__half* __restrict__ Xf, const __half* __restrict__ Yh,
                              const float* __restrict__ w, const float* __restrict__ b) {
    int row  = blockIdx.x * 8 + (threadIdx.x >> 5);
    int lane = threadIdx.x & 31;
    const uint4* xr = reinterpret_cast<const uint4*>(Xf + (size_t)row * E_);
    const uint4* yr = reinterpret_cast<const uint4*>(Yh + (size_t)row * E_);

    float vals[16];
    float s = 0.f, s2 = 0.f;
    #pragma unroll
    for (int j = 0; j < 2; j++) {
        uint4 xa = xr[lane + 32*j];
        uint4 ya = yr[lane + 32*j];
        const __half2* xh = reinterpret_cast<const __half2*>(&xa);
        const __half2* yh = reinterpret_cast<const __half2*>(&ya);
        #pragma unroll
        for (int q = 0; q < 4; q++) {
            float2 fx = __half22float2(xh[q]);
            float2 fy = __half22float2(yh[q]);
            float a0 = fx.x + fy.x, a1 = fx.y + fy.y;
            vals[j*8 + 2*q]     = a0;
            vals[j*8 + 2*q + 1] = a1;
            s  += a0 + a1;
            s2 += a0*a0 + a1*a1;
        }
    }
    #pragma unroll
    for (int o = 16; o; o >>= 1) {
        s  += __shfl_xor_sync(0xffffffffu, s,  o);
        s2 += __shfl_xor_sync(0xffffffffu, s2, o);
    }
    float mean = s * (1.0f / E_);
    float rstd = rsqrtf(s2 * (1.0f / E_) - mean*mean + 1e-5f);

    uint4* xw = reinterpret_cast<uint4*>(Xf + (size_t)row * E_);
    #pragma unroll
    for (int j = 0; j < 2; j++) {
        int base = (lane + 32*j) * 8;
        uint4 o;
        __half2* oh = reinterpret_cast<__half2*>(&o);
        #pragma unroll
        for (int q = 0; q < 4; q++) {
            float2 wv = *reinterpret_cast<const float2*>(w + base + 2*q);
            float2 bv = *reinterpret_cast<const float2*>(b + base + 2*q);
            float o0 = (vals[j*8 + 2*q]     - mean) * rstd * wv.x + bv.x;
            float o1 = (vals[j*8 + 2*q + 1] - mean) * rstd * wv.y + bv.y;
            __half2 h; h.x = __float2half_rn(o0); h.y = __float2half_rn(o1);
            oh[q] = h;
        }
        xw[lane + 32*j] = o;
    }
}

// ---------------- discriminator head (vectorized) ----------------
__global__ void disc_kernel(const float* __restrict__ bert,
                            const __half* __restrict__ posf,
                            const float* __restrict__ wd,
                            const float* __restrict__ bd,
                            float* __restrict__ out, int ntok) {
    int n = (blockIdx.x * blockDim.x + threadIdx.x) >> 5;
    int lane = threadIdx.x & 31;
    if (n >= ntok) return;
    float acc = 0.0f;
    const float4* br4 = reinterpret_cast<const float4*>(bert + (size_t)n * F_);
    const float4* wd4 = reinterpret_cast<const float4*>(wd);
    #pragma unroll
    for (int j = 0; j < 6; j++) {
        int idx = lane + 32*j;
        float4 v = br4[idx];
        float4 wv = wd4[idx];
        acc += v.x*wv.x + v.y*wv.y + v.z*wv.z + v.w*wv.w;
    }
    const uint4* pr4 = reinterpret_cast<const uint4*>(posf + (size_t)n * F_);
    #pragma unroll
    for (int j = 0; j < 3; j++) {
        int idx = lane + 32*j;
        uint4 u = pr4[idx];
        const __half2* ph = reinterpret_cast<const __half2*>(&u);
        const float* wp = wd + F_ + idx*8;
        #pragma unroll
        for (int q = 0; q < 4; q++) {
            float2 f = __half22float2(ph[q]);
            acc += f.x * wp[2*q] + f.y * wp[2*q + 1];
        }
    }
    #pragma unroll
    for (int o = 16; o; o >>= 1) acc += __shfl_xor_sync(0xffffffffu, acc, o);
    if (lane == 0) out[n] = 1.0f / (1.0f + expf(-(acc + bd[0])));
}

// ---------------- host orchestration ----------------
static inline int cdiv(int a, int b) { return (a + b - 1) / b; }

extern "C" void kernel_launch(void* const* d_in, const int* in_sizes, int n_in,
                              void* d_out, int out_size) {
    const int*   pos1  = (const int*)d_in[0];
    const int*   pos2  = (const int*)d_in[1];
    const float* bert  = (const float*)d_in[2];
    const float* fbase = (const float*)d_in[3];
    const float* emb   = (const float*)d_in[4];
    const float* wqkv  = (const float*)d_in[5];
    const float* bqkv  = (const float*)d_in[6];
    const float* wo    = (const float*)d_in[7];
    const float* bo    = (const float*)d_in[8];
    const float* ln1w  = (const float*)d_in[9];
    const float* ln1b  = (const float*)d_in[10];
    const float* ln2w  = (const float*)d_in[11];
    const float* ln2b  = (const float*)d_in[12];
    const float* w1    = (const float*)d_in[13];
    const float* b1    = (const float*)d_in[14];
    const float* w2    = (const float*)d_in[15];
    const float* b2    = (const float*)d_in[16];
    const float* wm    = (const float*)d_in[17];
    const float* wd    = (const float*)d_in[18];
    const float* bd    = (const float*)d_in[19];
    float* out = (float*)d_out;

    float *PE; int* SPAN;
    __half *Xf, *Yh, *QKVf, *CXf, *Hf, *POSFh, *WQf, *WOf, *W1f, *W2f, *WMf;
    cudaGetSymbolAddress((void**)&PE,    d_PE);
    cudaGetSymbolAddress((void**)&SPAN,  d_SPAN);
    cudaGetSymbolAddress((void**)&Xf,    d_Xf);
    cudaGetSymbolAddress((void**)&Yh,    d_Yh);
    cudaGetSymbolAddress((void**)&QKVf,  d_QKVf);
    cudaGetSymbolAddress((void**)&CXf,   d_CXf);
    cudaGetSymbolAddress((void**)&Hf,    d_Hf);
    cudaGetSymbolAddress((void**)&POSFh, d_POSFh);
    cudaGetSymbolAddress((void**)&WQf,   d_WQf);
    cudaGetSymbolAddress((void**)&WOf,   d_WOf);
    cudaGetSymbolAddress((void**)&W1f,   d_W1f);
    cudaGetSymbolAddress((void**)&W2f,   d_W2f);
    cudaGetSymbolAddress((void**)&WMf,   d_WMf);

    cudaFuncSetAttribute(gemm_tc, cudaFuncAttributeMaxDynamicSharedMemorySize, SMEM_GEMM);

    // launch 0: span + PE + convert wqkv (fused)
    spanpe_kernel<<<32 + PE_BLKS + CVTQ_BLKS, 512>>>(pos1, SPAN, PE, wqkv, WQf);
    // launch 1: build x
    build_x_kernel<<<NTOK/8, 256>>>(pos2, fbase, emb, SPAN, PE, Xf);

    const int MY = cdiv(NTOK, BM);   // 129
    bool cvt_rest_done = false;

    for (int l = 0; l < 2; l++) {
        const size_t oq = (size_t)l * 3*E_ * E_;
        const size_t oo = (size_t)l * E_ * E_;
        const size_t o1 = (size_t)l * DFF_ * E_;
        const size_t o2 = (size_t)l * E_ * DFF_;

        { dim3 g(3*E_/BN, MY);   // QKV -> fp16 (launch 2, layer 0)
          gemm_tc<<<g, NTHR_G, SMEM_GEMM>>>(Xf, WQf+oq,
              QKVf, NTOK, 3*E_, E_, bqkv + l*3*E_, 0); }

        attn_kernel<<<S_*NHEAD_, 256>>>(QKVf, CXf);   // launch 3 on layer 0 -> ncu

        if (!cvt_rest_done) {    // launch 4: convert wo,w1,w2,wm
            int n2 = 2*E_*E_/4, n3 = 2*DFF_*E_/4, n4 = 2*E_*DFF_/4, n5 = F_*E_/4;
            cvt4_kernel<<<cdiv(n2+n3+n4+n5, 256), 256>>>(
                wo, WOf, n2, w1, W1f, n3, w2, W2f, n4, wm, WMf, n5);
            cvt_rest_done = true;
        }

        { dim3 g(E_/BN, MY);     // Wo -> fp16 Y
          gemm_tc<<<g, NTHR_G, SMEM_GEMM>>>(CXf, WOf+oo,
              Yh, NTOK, E_, E_, bo + l*E_, 0); }

        add_ln_kernel<<<NTOK/8, 256>>>(Xf, Yh, ln1w + l*E_, ln1b + l*E_);

        { dim3 g(DFF_/BN, MY);   // FFN1 -> f16 H
          gemm_tc<<<g, NTHR_G, SMEM_GEMM>>>(Xf, W1f+o1,
              Hf, NTOK, DFF_, E_, b1 + l*DFF_, 1); }

        { dim3 g(E_/BN, MY);     // FFN2 -> fp16 Y
          gemm_tc<<<g, NTHR_G, SMEM_GEMM>>>(Hf, W2f+o2,
              Yh, NTOK, E_, DFF_, b2 + l*E_, 0); }

        add_ln_kernel<<<NTOK/8, 256>>>(Xf, Yh, ln2w + l*E_, ln2b + l*E_);
    }

    { dim3 g(F_/BN, MY);         // pos_feature = tanh(X @ wm^T), fp16 out
      gemm_tc<<<g, NTHR_G, SMEM_GEMM>>>(Xf, WMf,
          POSFh, NTOK, F_, E_, nullptr, 2); }

    disc_kernel<<<cdiv(NTOK*32, 256), 256>>>(bert, POSFh, wd, bd, out, NTOK);
}